// round 1
// baseline (speedup 1.0000x reference)
#include <cuda_runtime.h>
#include <cuda_bf16.h>
#include <math.h>

// Problem constants
#define T_DIM 2048
#define C_DIM 1024
#define H_DIM 16
#define D_DIM 64
#define QKV_N (3 * C_DIM)   // 3072

// Scratch (allocation-free: __device__ globals)
__device__ float g_qkv[T_DIM * QKV_N];   // [T, 3C]
__device__ float g_y[T_DIM * C_DIM];     // [T, C] attention output

// ---------------------------------------------------------------------------
// SGEMM: C[M,N] = A[M,K] @ B[K,N] + bias[N]
// 128x128 block tile, BK=8, 8x8 per-thread microtile, 256 threads.
// ---------------------------------------------------------------------------
#define BM 128
#define BN 128
#define BK 8
#define TM 8
#define TN 8

__global__ __launch_bounds__(256) void sgemm_bias(
    int M, int N, int K,
    const float* __restrict__ A, const float* __restrict__ B,
    const float* __restrict__ bias, float* __restrict__ C)
{
    __shared__ float As[BK * BM];   // stored transposed: As[k][m]
    __shared__ float Bs[BK * BN];

    const int crow = blockIdx.y * BM;
    const int ccol = blockIdx.x * BN;
    const int tid  = threadIdx.x;

    const int threadRow = tid / (BN / TN);   // 0..15
    const int threadCol = tid % (BN / TN);   // 0..15

    const int innerRowA = tid / (BK / 4);    // 0..127
    const int innerColA = tid % (BK / 4);    // 0..1
    const int innerRowB = tid / (BN / 4);    // 0..7
    const int innerColB = tid % (BN / 4);    // 0..31

    A += (size_t)crow * K;
    B += ccol;

    float acc[TM][TN] = {};
    float regM[TM], regN[TN];

    for (int k0 = 0; k0 < K; k0 += BK) {
        // Load A tile (128x8) as float4, store transposed
        float4 a4 = *reinterpret_cast<const float4*>(
            &A[(size_t)innerRowA * K + k0 + innerColA * 4]);
        As[(innerColA * 4 + 0) * BM + innerRowA] = a4.x;
        As[(innerColA * 4 + 1) * BM + innerRowA] = a4.y;
        As[(innerColA * 4 + 2) * BM + innerRowA] = a4.z;
        As[(innerColA * 4 + 3) * BM + innerRowA] = a4.w;
        // Load B tile (8x128) as float4
        *reinterpret_cast<float4*>(&Bs[innerRowB * BN + innerColB * 4]) =
            *reinterpret_cast<const float4*>(
                &B[(size_t)(k0 + innerRowB) * N + innerColB * 4]);
        __syncthreads();

        #pragma unroll
        for (int k = 0; k < BK; k++) {
            #pragma unroll
            for (int i = 0; i < TM; i++) regM[i] = As[k * BM + threadRow * TM + i];
            #pragma unroll
            for (int j = 0; j < TN; j++) regN[j] = Bs[k * BN + threadCol * TN + j];
            #pragma unroll
            for (int i = 0; i < TM; i++)
                #pragma unroll
                for (int j = 0; j < TN; j++)
                    acc[i][j] += regM[i] * regN[j];
        }
        __syncthreads();
    }

    #pragma unroll
    for (int i = 0; i < TM; i++) {
        const int r = crow + threadRow * TM + i;
        #pragma unroll
        for (int j = 0; j < TN; j += 4) {
            const int c = ccol + threadCol * TN + j;
            float4 o;
            o.x = acc[i][j + 0] + bias[c + 0];
            o.y = acc[i][j + 1] + bias[c + 1];
            o.z = acc[i][j + 2] + bias[c + 2];
            o.w = acc[i][j + 3] + bias[c + 3];
            *reinterpret_cast<float4*>(&C[(size_t)r * N + c]) = o;
        }
    }
}

// ---------------------------------------------------------------------------
// Attention: flash-style, one thread per query row.
// Block: 64 threads = 64 queries of one head. K/V tiles 32x64 in shared.
// Online softmax, fp32 accumulate.
// ---------------------------------------------------------------------------
#define ATT_BQ 64
#define ATT_BS 32

__global__ __launch_bounds__(ATT_BQ) void attn_kernel(
    const float* __restrict__ qkv, float* __restrict__ y)
{
    const int h   = blockIdx.y;
    const int q0  = blockIdx.x * ATT_BQ;
    const int tid = threadIdx.x;
    const float scale = 0.125f;  // 1/sqrt(64)

    __shared__ float Ks[ATT_BS][D_DIM];
    __shared__ float Vs[ATT_BS][D_DIM];

    float q[D_DIM], o[D_DIM];
    const float* qrow = qkv + (size_t)(q0 + tid) * QKV_N + h * D_DIM;
    #pragma unroll
    for (int d = 0; d < D_DIM; d++) {
        q[d] = qrow[d] * scale;
        o[d] = 0.0f;
    }
    float m = -INFINITY, l = 0.0f;

    const float* kbase = qkv + C_DIM     + h * D_DIM;
    const float* vbase = qkv + 2 * C_DIM + h * D_DIM;

    for (int s0 = 0; s0 < T_DIM; s0 += ATT_BS) {
        __syncthreads();
        // cooperative coalesced tile load: 32x64 floats each for K and V
        for (int j = tid; j < ATT_BS * D_DIM; j += ATT_BQ) {
            const int r = j >> 6;
            const int c = j & 63;
            Ks[r][c] = kbase[(size_t)(s0 + r) * QKV_N + c];
            Vs[r][c] = vbase[(size_t)(s0 + r) * QKV_N + c];
        }
        __syncthreads();

        float sc[ATT_BS];
        float mt = m;
        #pragma unroll
        for (int s = 0; s < ATT_BS; s++) {
            float a = 0.0f;
            #pragma unroll
            for (int d = 0; d < D_DIM; d++) a += q[d] * Ks[s][d];
            sc[s] = a;
            mt = fmaxf(mt, a);
        }
        const float corr = __expf(m - mt);
        m = mt;
        l *= corr;
        #pragma unroll
        for (int d = 0; d < D_DIM; d++) o[d] *= corr;
        #pragma unroll
        for (int s = 0; s < ATT_BS; s++) {
            const float p = __expf(sc[s] - m);
            l += p;
            #pragma unroll
            for (int d = 0; d < D_DIM; d++) o[d] += p * Vs[s][d];
        }
    }

    const float inv = 1.0f / l;
    float* yrow = y + (size_t)(q0 + tid) * C_DIM + h * D_DIM;
    #pragma unroll
    for (int d = 0; d < D_DIM; d++) yrow[d] = o[d] * inv;
}

// ---------------------------------------------------------------------------
// kernel_launch
// inputs (metadata order): x [T,C], W_qkv [C,3C], b_qkv [3C], W_proj [C,C], b_proj [C]
// output: [T,C] float32
// ---------------------------------------------------------------------------
extern "C" void kernel_launch(void* const* d_in, const int* in_sizes, int n_in,
                              void* d_out, int out_size)
{
    const float* x      = (const float*)d_in[0];
    const float* W_qkv  = (const float*)d_in[1];
    const float* b_qkv  = (const float*)d_in[2];
    const float* W_proj = (const float*)d_in[3];
    const float* b_proj = (const float*)d_in[4];
    float* out = (float*)d_out;

    float *qkv, *y;
    cudaGetSymbolAddress((void**)&qkv, g_qkv);
    cudaGetSymbolAddress((void**)&y, g_y);

    // 1) QKV projection: [T,3C] = x @ W_qkv + b_qkv
    sgemm_bias<<<dim3(QKV_N / BN, T_DIM / BM), 256>>>(
        T_DIM, QKV_N, C_DIM, x, W_qkv, b_qkv, qkv);

    // 2) Attention: y[T,C]
    attn_kernel<<<dim3(T_DIM / ATT_BQ, H_DIM), ATT_BQ>>>(qkv, y);

    // 3) Output projection: out = y @ W_proj + b_proj
    sgemm_bias<<<dim3(C_DIM / BN, T_DIM / BM), 256>>>(
        T_DIM, C_DIM, C_DIM, y, W_proj, b_proj, out);
}

// round 2
// speedup vs baseline: 1.4335x; 1.4335x over previous
#include <cuda_runtime.h>
#include <cuda_bf16.h>
#include <math.h>
#include <stdint.h>

// Problem constants
#define T_DIM 2048
#define C_DIM 1024
#define H_DIM 16
#define D_DIM 64
#define QKV_N (3 * C_DIM)   // 3072

// Scratch (allocation-free: __device__ globals)
__device__ float g_qkv[T_DIM * QKV_N];   // [T, 3C]
__device__ float g_y[T_DIM * C_DIM];     // [T, C] attention output

// ---------------------------------------------------------------------------
// TF32 tensor-core GEMM: C[M,N] = A[M,K] @ B[K,N] + bias[N]
// Block tile 128x128, K-chunk 32. 8 warps (2x4), warp tile 64x32.
// mma.sync.aligned.m16n8k8.row.col.f32.tf32.tf32.f32
// ---------------------------------------------------------------------------
#define GBM 128
#define GBN 128
#define GBK 32
#define AS_STRIDE 36    // 32 + 4 pad  -> frag-load banks = (4*gid + tig) unique
#define BS_STRIDE 136   // 128 + 8 pad -> frag-load banks = (8*tig + gid) unique

__device__ __forceinline__ uint32_t f2tf32(float x) {
    uint32_t r;
    asm("cvt.rna.tf32.f32 %0, %1;" : "=r"(r) : "f"(x));
    return r;
}

__device__ __forceinline__ void mma_tf32(float* d, const uint32_t* a, const uint32_t* b) {
    asm volatile(
        "mma.sync.aligned.m16n8k8.row.col.f32.tf32.tf32.f32 "
        "{%0,%1,%2,%3}, {%4,%5,%6,%7}, {%8,%9}, {%0,%1,%2,%3};"
        : "+f"(d[0]), "+f"(d[1]), "+f"(d[2]), "+f"(d[3])
        : "r"(a[0]), "r"(a[1]), "r"(a[2]), "r"(a[3]), "r"(b[0]), "r"(b[1]));
}

__global__ __launch_bounds__(256) void gemm_tf32_bias(
    int M, int N, int K,
    const float* __restrict__ A, const float* __restrict__ B,
    const float* __restrict__ bias, float* __restrict__ C)
{
    __shared__ uint32_t As[GBM * AS_STRIDE];   // [m][k], row-major, padded
    __shared__ uint32_t Bs[GBK * BS_STRIDE];   // [k][n], row-major, padded

    const int tid  = threadIdx.x;
    const int lane = tid & 31;
    const int warp = tid >> 5;
    const int gid  = lane >> 2;   // group id 0..7
    const int tig  = lane & 3;    // thread-in-group 0..3

    const int wm = warp & 1;      // warp row 0..1   -> 64 rows each
    const int wn = warp >> 1;     // warp col 0..3   -> 32 cols each

    const int crow = blockIdx.y * GBM;
    const int ccol = blockIdx.x * GBN;

    // staging thread maps
    const int arow = tid >> 3;         // 0..31 (A: 128x32, float4 per 8 cols)
    const int acol4 = tid & 7;         // 0..7
    const int brow = tid >> 6;         // 0..3 (B: 32x128, step 8)... actually tid/32 below
    const int brow32 = tid >> 5;       // 0..7
    const int bcol4 = tid & 31;        // 0..31
    (void)brow;

    float acc[4][4][4];
    #pragma unroll
    for (int i = 0; i < 4; i++)
        #pragma unroll
        for (int j = 0; j < 4; j++)
            #pragma unroll
            for (int r = 0; r < 4; r++) acc[i][j][r] = 0.0f;

    for (int k0 = 0; k0 < K; k0 += GBK) {
        // ---- stage A: rows crow..crow+127, cols k0..k0+31 ----
        #pragma unroll
        for (int p = 0; p < 4; p++) {
            const int r = arow + p * 32;
            float4 v = *reinterpret_cast<const float4*>(
                &A[(size_t)(crow + r) * K + k0 + acol4 * 4]);
            uint32_t* dst = &As[r * AS_STRIDE + acol4 * 4];
            dst[0] = f2tf32(v.x); dst[1] = f2tf32(v.y);
            dst[2] = f2tf32(v.z); dst[3] = f2tf32(v.w);
        }
        // ---- stage B: rows k0..k0+31, cols ccol..ccol+127 ----
        #pragma unroll
        for (int p = 0; p < 4; p++) {
            const int r = brow32 + p * 8;
            float4 v = *reinterpret_cast<const float4*>(
                &B[(size_t)(k0 + r) * N + ccol + bcol4 * 4]);
            uint32_t* dst = &Bs[r * BS_STRIDE + bcol4 * 4];
            dst[0] = f2tf32(v.x); dst[1] = f2tf32(v.y);
            dst[2] = f2tf32(v.z); dst[3] = f2tf32(v.w);
        }
        __syncthreads();

        #pragma unroll
        for (int kk = 0; kk < 4; kk++) {
            const int kb = kk * 8;
            uint32_t af[4][4], bf[4][2];
            #pragma unroll
            for (int mi = 0; mi < 4; mi++) {
                const int m = wm * 64 + mi * 16 + gid;
                af[mi][0] = As[(m    ) * AS_STRIDE + kb + tig    ];
                af[mi][1] = As[(m + 8) * AS_STRIDE + kb + tig    ];
                af[mi][2] = As[(m    ) * AS_STRIDE + kb + tig + 4];
                af[mi][3] = As[(m + 8) * AS_STRIDE + kb + tig + 4];
            }
            #pragma unroll
            for (int ni = 0; ni < 4; ni++) {
                const int n = wn * 32 + ni * 8 + gid;
                bf[ni][0] = Bs[(kb + tig    ) * BS_STRIDE + n];
                bf[ni][1] = Bs[(kb + tig + 4) * BS_STRIDE + n];
            }
            #pragma unroll
            for (int mi = 0; mi < 4; mi++)
                #pragma unroll
                for (int ni = 0; ni < 4; ni++)
                    mma_tf32(acc[mi][ni], af[mi], bf[ni]);
        }
        __syncthreads();
    }

    // ---- epilogue: add bias, store ----
    #pragma unroll
    for (int mi = 0; mi < 4; mi++) {
        const int r = crow + wm * 64 + mi * 16 + gid;
        #pragma unroll
        for (int ni = 0; ni < 4; ni++) {
            const int c = ccol + wn * 32 + ni * 8 + 2 * tig;
            const float b0 = bias[c], b1 = bias[c + 1];
            float2 o1 = make_float2(acc[mi][ni][0] + b0, acc[mi][ni][1] + b1);
            float2 o2 = make_float2(acc[mi][ni][2] + b0, acc[mi][ni][3] + b1);
            *reinterpret_cast<float2*>(&C[(size_t)r * N + c]) = o1;
            *reinterpret_cast<float2*>(&C[(size_t)(r + 8) * N + c]) = o2;
        }
    }
}

// ---------------------------------------------------------------------------
// Attention: flash-style, one thread per query row, float4 shared reads.
// ---------------------------------------------------------------------------
#define ATT_BQ 64
#define ATT_BS 32

__global__ __launch_bounds__(ATT_BQ) void attn_kernel(
    const float* __restrict__ qkv, float* __restrict__ y)
{
    const int h   = blockIdx.y;
    const int q0  = blockIdx.x * ATT_BQ;
    const int tid = threadIdx.x;
    const float scale = 0.125f;  // 1/sqrt(64)

    __shared__ float4 Ks[ATT_BS][D_DIM / 4];
    __shared__ float4 Vs[ATT_BS][D_DIM / 4];

    float q[D_DIM], o[D_DIM];
    const float* qrow = qkv + (size_t)(q0 + tid) * QKV_N + h * D_DIM;
    #pragma unroll
    for (int d = 0; d < D_DIM; d++) {
        q[d] = qrow[d] * scale;
        o[d] = 0.0f;
    }
    float m = -INFINITY, l = 0.0f;

    const float* kbase = qkv + C_DIM     + h * D_DIM;
    const float* vbase = qkv + 2 * C_DIM + h * D_DIM;

    for (int s0 = 0; s0 < T_DIM; s0 += ATT_BS) {
        __syncthreads();
        // cooperative float4 tile load: 32 rows x 16 float4 each for K and V
        #pragma unroll
        for (int j = tid; j < ATT_BS * 16; j += ATT_BQ) {
            const int r  = j >> 4;
            const int c4 = j & 15;
            Ks[r][c4] = *reinterpret_cast<const float4*>(
                &kbase[(size_t)(s0 + r) * QKV_N + c4 * 4]);
            Vs[r][c4] = *reinterpret_cast<const float4*>(
                &vbase[(size_t)(s0 + r) * QKV_N + c4 * 4]);
        }
        __syncthreads();

        float sc[ATT_BS];
        float mt = m;
        #pragma unroll
        for (int s = 0; s < ATT_BS; s++) {
            float a0 = 0.0f, a1 = 0.0f;
            #pragma unroll
            for (int d4 = 0; d4 < 16; d4 += 2) {
                float4 k0v = Ks[s][d4];
                float4 k1v = Ks[s][d4 + 1];
                a0 += q[4 * d4 + 0] * k0v.x + q[4 * d4 + 1] * k0v.y
                    + q[4 * d4 + 2] * k0v.z + q[4 * d4 + 3] * k0v.w;
                a1 += q[4 * d4 + 4] * k1v.x + q[4 * d4 + 5] * k1v.y
                    + q[4 * d4 + 6] * k1v.z + q[4 * d4 + 7] * k1v.w;
            }
            const float a = a0 + a1;
            sc[s] = a;
            mt = fmaxf(mt, a);
        }
        const float corr = __expf(m - mt);
        m = mt;
        l *= corr;
        #pragma unroll
        for (int d = 0; d < D_DIM; d++) o[d] *= corr;
        #pragma unroll
        for (int s = 0; s < ATT_BS; s++) {
            const float p = __expf(sc[s] - m);
            l += p;
            #pragma unroll
            for (int d4 = 0; d4 < 16; d4++) {
                float4 vv = Vs[s][d4];
                o[4 * d4 + 0] += p * vv.x;
                o[4 * d4 + 1] += p * vv.y;
                o[4 * d4 + 2] += p * vv.z;
                o[4 * d4 + 3] += p * vv.w;
            }
        }
    }

    const float inv = 1.0f / l;
    float* yrow = y + (size_t)(q0 + tid) * C_DIM + h * D_DIM;
    #pragma unroll
    for (int d = 0; d < D_DIM; d++) yrow[d] = o[d] * inv;
}

// ---------------------------------------------------------------------------
// kernel_launch
// inputs: x [T,C], W_qkv [C,3C], b_qkv [3C], W_proj [C,C], b_proj [C]
// output: [T,C] float32
// ---------------------------------------------------------------------------
extern "C" void kernel_launch(void* const* d_in, const int* in_sizes, int n_in,
                              void* d_out, int out_size)
{
    const float* x      = (const float*)d_in[0];
    const float* W_qkv  = (const float*)d_in[1];
    const float* b_qkv  = (const float*)d_in[2];
    const float* W_proj = (const float*)d_in[3];
    const float* b_proj = (const float*)d_in[4];
    float* out = (float*)d_out;

    float *qkv, *y;
    cudaGetSymbolAddress((void**)&qkv, g_qkv);
    cudaGetSymbolAddress((void**)&y, g_y);

    // 1) QKV projection: [T,3C] = x @ W_qkv + b_qkv
    gemm_tf32_bias<<<dim3(QKV_N / GBN, T_DIM / GBM), 256>>>(
        T_DIM, QKV_N, C_DIM, x, W_qkv, b_qkv, qkv);

    // 2) Attention: y[T,C]
    attn_kernel<<<dim3(T_DIM / ATT_BQ, H_DIM), ATT_BQ>>>(qkv, y);

    // 3) Output projection: out = y @ W_proj + b_proj
    gemm_tf32_bias<<<dim3(C_DIM / GBN, T_DIM / GBM), 256>>>(
        T_DIM, C_DIM, C_DIM, y, W_proj, b_proj, out);
}

// round 3
// speedup vs baseline: 1.4657x; 1.0225x over previous
#include <cuda_runtime.h>
#include <cuda_bf16.h>
#include <math.h>
#include <stdint.h>

// Problem constants
#define T_DIM 2048
#define C_DIM 1024
#define H_DIM 16
#define D_DIM 64
#define QKV_N (3 * C_DIM)   // 3072

// Scratch (allocation-free: __device__ globals)
__device__ float g_qkv[T_DIM * QKV_N];   // [T, 3C]
__device__ float g_y[T_DIM * C_DIM];     // [T, C] attention output

// ---------------------------------------------------------------------------
// TF32 tensor-core GEMM: C[M,N] = A[M,K] @ B[K,N] + bias[N]
// Block tile 128x128, K-chunk 32. 8 warps (2x4), warp tile 64x32.
// mma.sync.aligned.m16n8k8.row.col.f32.tf32.tf32.f32
// ---------------------------------------------------------------------------
#define GBM 128
#define GBN 128
#define GBK 32
#define AS_STRIDE 36    // 32 + 4 pad  -> frag-load banks = (4*gid + tig) unique
#define BS_STRIDE 136   // 128 + 8 pad -> frag-load banks = (8*tig + gid) unique

__device__ __forceinline__ uint32_t f2tf32(float x) {
    uint32_t r;
    asm("cvt.rna.tf32.f32 %0, %1;" : "=r"(r) : "f"(x));
    return r;
}

__device__ __forceinline__ void mma_tf32(float* d, const uint32_t* a, const uint32_t* b) {
    asm volatile(
        "mma.sync.aligned.m16n8k8.row.col.f32.tf32.tf32.f32 "
        "{%0,%1,%2,%3}, {%4,%5,%6,%7}, {%8,%9}, {%0,%1,%2,%3};"
        : "+f"(d[0]), "+f"(d[1]), "+f"(d[2]), "+f"(d[3])
        : "r"(a[0]), "r"(a[1]), "r"(a[2]), "r"(a[3]), "r"(b[0]), "r"(b[1]));
}

__global__ __launch_bounds__(256) void gemm_tf32_bias(
    int M, int N, int K,
    const float* __restrict__ A, const float* __restrict__ B,
    const float* __restrict__ bias, float* __restrict__ C)
{
    __shared__ uint32_t As[GBM * AS_STRIDE];   // [m][k], row-major, padded
    __shared__ uint32_t Bs[GBK * BS_STRIDE];   // [k][n], row-major, padded

    const int tid  = threadIdx.x;
    const int lane = tid & 31;
    const int warp = tid >> 5;
    const int gid  = lane >> 2;   // group id 0..7
    const int tig  = lane & 3;    // thread-in-group 0..3

    const int wm = warp & 1;      // warp row 0..1   -> 64 rows each
    const int wn = warp >> 1;     // warp col 0..3   -> 32 cols each

    const int crow = blockIdx.y * GBM;
    const int ccol = blockIdx.x * GBN;

    // staging thread maps
    const int arow = tid >> 3;         // 0..31 (A: 128x32, float4 per 8 cols)
    const int acol4 = tid & 7;         // 0..7
    const int brow = tid >> 6;         // 0..3 (B: 32x128, step 8)... actually tid/32 below
    const int brow32 = tid >> 5;       // 0..7
    const int bcol4 = tid & 31;        // 0..31
    (void)brow;

    float acc[4][4][4];
    #pragma unroll
    for (int i = 0; i < 4; i++)
        #pragma unroll
        for (int j = 0; j < 4; j++)
            #pragma unroll
            for (int r = 0; r < 4; r++) acc[i][j][r] = 0.0f;

    for (int k0 = 0; k0 < K; k0 += GBK) {
        // ---- stage A: rows crow..crow+127, cols k0..k0+31 ----
        #pragma unroll
        for (int p = 0; p < 4; p++) {
            const int r = arow + p * 32;
            float4 v = *reinterpret_cast<const float4*>(
                &A[(size_t)(crow + r) * K + k0 + acol4 * 4]);
            uint32_t* dst = &As[r * AS_STRIDE + acol4 * 4];
            dst[0] = f2tf32(v.x); dst[1] = f2tf32(v.y);
            dst[2] = f2tf32(v.z); dst[3] = f2tf32(v.w);
        }
        // ---- stage B: rows k0..k0+31, cols ccol..ccol+127 ----
        #pragma unroll
        for (int p = 0; p < 4; p++) {
            const int r = brow32 + p * 8;
            float4 v = *reinterpret_cast<const float4*>(
                &B[(size_t)(k0 + r) * N + ccol + bcol4 * 4]);
            uint32_t* dst = &Bs[r * BS_STRIDE + bcol4 * 4];
            dst[0] = f2tf32(v.x); dst[1] = f2tf32(v.y);
            dst[2] = f2tf32(v.z); dst[3] = f2tf32(v.w);
        }
        __syncthreads();

        #pragma unroll
        for (int kk = 0; kk < 4; kk++) {
            const int kb = kk * 8;
            uint32_t af[4][4], bf[4][2];
            #pragma unroll
            for (int mi = 0; mi < 4; mi++) {
                const int m = wm * 64 + mi * 16 + gid;
                af[mi][0] = As[(m    ) * AS_STRIDE + kb + tig    ];
                af[mi][1] = As[(m + 8) * AS_STRIDE + kb + tig    ];
                af[mi][2] = As[(m    ) * AS_STRIDE + kb + tig + 4];
                af[mi][3] = As[(m + 8) * AS_STRIDE + kb + tig + 4];
            }
            #pragma unroll
            for (int ni = 0; ni < 4; ni++) {
                const int n = wn * 32 + ni * 8 + gid;
                bf[ni][0] = Bs[(kb + tig    ) * BS_STRIDE + n];
                bf[ni][1] = Bs[(kb + tig + 4) * BS_STRIDE + n];
            }
            #pragma unroll
            for (int mi = 0; mi < 4; mi++)
                #pragma unroll
                for (int ni = 0; ni < 4; ni++)
                    mma_tf32(acc[mi][ni], af[mi], bf[ni]);
        }
        __syncthreads();
    }

    // ---- epilogue: add bias, store ----
    #pragma unroll
    for (int mi = 0; mi < 4; mi++) {
        const int r = crow + wm * 64 + mi * 16 + gid;
        #pragma unroll
        for (int ni = 0; ni < 4; ni++) {
            const int c = ccol + wn * 32 + ni * 8 + 2 * tig;
            const float b0 = bias[c], b1 = bias[c + 1];
            float2 o1 = make_float2(acc[mi][ni][0] + b0, acc[mi][ni][1] + b1);
            float2 o2 = make_float2(acc[mi][ni][2] + b0, acc[mi][ni][3] + b1);
            *reinterpret_cast<float2*>(&C[(size_t)r * N + c]) = o1;
            *reinterpret_cast<float2*>(&C[(size_t)(r + 8) * N + c]) = o2;
        }
    }
}

// ---------------------------------------------------------------------------
// Attention: flash-style, one thread per query row, float4 shared reads.
// ---------------------------------------------------------------------------
#define ATT_BQ 64
#define ATT_BS 32

__global__ __launch_bounds__(ATT_BQ) void attn_kernel(
    const float* __restrict__ qkv, float* __restrict__ y)
{
    const int h   = blockIdx.y;
    const int q0  = blockIdx.x * ATT_BQ;
    const int tid = threadIdx.x;
    const float scale = 0.125f;  // 1/sqrt(64)

    __shared__ float4 Ks[ATT_BS][D_DIM / 4];
    __shared__ float4 Vs[ATT_BS][D_DIM / 4];

    float q[D_DIM], o[D_DIM];
    const float* qrow = qkv + (size_t)(q0 + tid) * QKV_N + h * D_DIM;
    #pragma unroll
    for (int d = 0; d < D_DIM; d++) {
        q[d] = qrow[d] * scale;
        o[d] = 0.0f;
    }
    float m = -INFINITY, l = 0.0f;

    const float* kbase = qkv + C_DIM     + h * D_DIM;
    const float* vbase = qkv + 2 * C_DIM + h * D_DIM;

    for (int s0 = 0; s0 < T_DIM; s0 += ATT_BS) {
        __syncthreads();
        // cooperative float4 tile load: 32 rows x 16 float4 each for K and V
        #pragma unroll
        for (int j = tid; j < ATT_BS * 16; j += ATT_BQ) {
            const int r  = j >> 4;
            const int c4 = j & 15;
            Ks[r][c4] = *reinterpret_cast<const float4*>(
                &kbase[(size_t)(s0 + r) * QKV_N + c4 * 4]);
            Vs[r][c4] = *reinterpret_cast<const float4*>(
                &vbase[(size_t)(s0 + r) * QKV_N + c4 * 4]);
        }
        __syncthreads();

        float sc[ATT_BS];
        float mt = m;
        #pragma unroll
        for (int s = 0; s < ATT_BS; s++) {
            float a0 = 0.0f, a1 = 0.0f;
            #pragma unroll
            for (int d4 = 0; d4 < 16; d4 += 2) {
                float4 k0v = Ks[s][d4];
                float4 k1v = Ks[s][d4 + 1];
                a0 += q[4 * d4 + 0] * k0v.x + q[4 * d4 + 1] * k0v.y
                    + q[4 * d4 + 2] * k0v.z + q[4 * d4 + 3] * k0v.w;
                a1 += q[4 * d4 + 4] * k1v.x + q[4 * d4 + 5] * k1v.y
                    + q[4 * d4 + 6] * k1v.z + q[4 * d4 + 7] * k1v.w;
            }
            const float a = a0 + a1;
            sc[s] = a;
            mt = fmaxf(mt, a);
        }
        const float corr = __expf(m - mt);
        m = mt;
        l *= corr;
        #pragma unroll
        for (int d = 0; d < D_DIM; d++) o[d] *= corr;
        #pragma unroll
        for (int s = 0; s < ATT_BS; s++) {
            const float p = __expf(sc[s] - m);
            l += p;
            #pragma unroll
            for (int d4 = 0; d4 < 16; d4++) {
                float4 vv = Vs[s][d4];
                o[4 * d4 + 0] += p * vv.x;
                o[4 * d4 + 1] += p * vv.y;
                o[4 * d4 + 2] += p * vv.z;
                o[4 * d4 + 3] += p * vv.w;
            }
        }
    }

    const float inv = 1.0f / l;
    float* yrow = y + (size_t)(q0 + tid) * C_DIM + h * D_DIM;
    #pragma unroll
    for (int d = 0; d < D_DIM; d++) yrow[d] = o[d] * inv;
}

// ---------------------------------------------------------------------------
// kernel_launch
// inputs: x [T,C], W_qkv [C,3C], b_qkv [3C], W_proj [C,C], b_proj [C]
// output: [T,C] float32
// ---------------------------------------------------------------------------
extern "C" void kernel_launch(void* const* d_in, const int* in_sizes, int n_in,
                              void* d_out, int out_size)
{
    const float* x      = (const float*)d_in[0];
    const float* W_qkv  = (const float*)d_in[1];
    const float* b_qkv  = (const float*)d_in[2];
    const float* W_proj = (const float*)d_in[3];
    const float* b_proj = (const float*)d_in[4];
    float* out = (float*)d_out;

    float *qkv, *y;
    cudaGetSymbolAddress((void**)&qkv, g_qkv);
    cudaGetSymbolAddress((void**)&y, g_y);

    // 1) QKV projection: [T,3C] = x @ W_qkv + b_qkv
    gemm_tf32_bias<<<dim3(QKV_N / GBN, T_DIM / GBM), 256>>>(
        T_DIM, QKV_N, C_DIM, x, W_qkv, b_qkv, qkv);

    // 2) Attention: y[T,C]
    attn_kernel<<<dim3(T_DIM / ATT_BQ, H_DIM), ATT_BQ>>>(qkv, y);

    // 3) Output projection: out = y @ W_proj + b_proj
    gemm_tf32_bias<<<dim3(C_DIM / GBN, T_DIM / GBM), 256>>>(
        T_DIM, C_DIM, C_DIM, y, W_proj, b_proj, out);
}

// round 4
// speedup vs baseline: 1.4780x; 1.0083x over previous
#include <cuda_runtime.h>
#include <cuda_bf16.h>
#include <math.h>
#include <stdint.h>

// Problem constants
#define T_DIM 2048
#define C_DIM 1024
#define H_DIM 16
#define D_DIM 64
#define QKV_N (3 * C_DIM)   // 3072

// Scratch (allocation-free: __device__ globals)
__device__ float g_qkv[T_DIM * QKV_N];   // [T, 3C]
__device__ float g_y[T_DIM * C_DIM];     // [T, C] attention output

// ---------------------------------------------------------------------------
// TF32 tensor-core GEMM: C[M,N] = A[M,K] @ B[K,N] + bias[N]
// Block tile 128x128, K-chunk 32. 8 warps (2x4), warp tile 64x32.
// mma.sync.aligned.m16n8k8.row.col.f32.tf32.tf32.f32
// ---------------------------------------------------------------------------
#define GBM 128
#define GBN 128
#define GBK 32
#define AS_STRIDE 36    // 32 + 4 pad  -> frag-load banks = (4*gid + tig) unique
#define BS_STRIDE 136   // 128 + 8 pad -> frag-load banks = (8*tig + gid) unique

__device__ __forceinline__ uint32_t f2tf32(float x) {
    uint32_t r;
    asm("cvt.rna.tf32.f32 %0, %1;" : "=r"(r) : "f"(x));
    return r;
}

__device__ __forceinline__ void mma_tf32(float* d, const uint32_t* a, const uint32_t* b) {
    asm volatile(
        "mma.sync.aligned.m16n8k8.row.col.f32.tf32.tf32.f32 "
        "{%0,%1,%2,%3}, {%4,%5,%6,%7}, {%8,%9}, {%0,%1,%2,%3};"
        : "+f"(d[0]), "+f"(d[1]), "+f"(d[2]), "+f"(d[3])
        : "r"(a[0]), "r"(a[1]), "r"(a[2]), "r"(a[3]), "r"(b[0]), "r"(b[1]));
}

__global__ __launch_bounds__(256) void gemm_tf32_bias(
    int M, int N, int K,
    const float* __restrict__ A, const float* __restrict__ B,
    const float* __restrict__ bias, float* __restrict__ C)
{
    __shared__ uint32_t As[GBM * AS_STRIDE];   // [m][k], row-major, padded
    __shared__ uint32_t Bs[GBK * BS_STRIDE];   // [k][n], row-major, padded

    const int tid  = threadIdx.x;
    const int lane = tid & 31;
    const int warp = tid >> 5;
    const int gid  = lane >> 2;   // group id 0..7
    const int tig  = lane & 3;    // thread-in-group 0..3

    const int wm = warp & 1;      // warp row 0..1   -> 64 rows each
    const int wn = warp >> 1;     // warp col 0..3   -> 32 cols each

    const int crow = blockIdx.y * GBM;
    const int ccol = blockIdx.x * GBN;

    // staging thread maps
    const int arow = tid >> 3;         // 0..31 (A: 128x32, float4 per 8 cols)
    const int acol4 = tid & 7;         // 0..7
    const int brow = tid >> 6;         // 0..3 (B: 32x128, step 8)... actually tid/32 below
    const int brow32 = tid >> 5;       // 0..7
    const int bcol4 = tid & 31;        // 0..31
    (void)brow;

    float acc[4][4][4];
    #pragma unroll
    for (int i = 0; i < 4; i++)
        #pragma unroll
        for (int j = 0; j < 4; j++)
            #pragma unroll
            for (int r = 0; r < 4; r++) acc[i][j][r] = 0.0f;

    for (int k0 = 0; k0 < K; k0 += GBK) {
        // ---- stage A: rows crow..crow+127, cols k0..k0+31 ----
        #pragma unroll
        for (int p = 0; p < 4; p++) {
            const int r = arow + p * 32;
            float4 v = *reinterpret_cast<const float4*>(
                &A[(size_t)(crow + r) * K + k0 + acol4 * 4]);
            uint32_t* dst = &As[r * AS_STRIDE + acol4 * 4];
            dst[0] = f2tf32(v.x); dst[1] = f2tf32(v.y);
            dst[2] = f2tf32(v.z); dst[3] = f2tf32(v.w);
        }
        // ---- stage B: rows k0..k0+31, cols ccol..ccol+127 ----
        #pragma unroll
        for (int p = 0; p < 4; p++) {
            const int r = brow32 + p * 8;
            float4 v = *reinterpret_cast<const float4*>(
                &B[(size_t)(k0 + r) * N + ccol + bcol4 * 4]);
            uint32_t* dst = &Bs[r * BS_STRIDE + bcol4 * 4];
            dst[0] = f2tf32(v.x); dst[1] = f2tf32(v.y);
            dst[2] = f2tf32(v.z); dst[3] = f2tf32(v.w);
        }
        __syncthreads();

        #pragma unroll
        for (int kk = 0; kk < 4; kk++) {
            const int kb = kk * 8;
            uint32_t af[4][4], bf[4][2];
            #pragma unroll
            for (int mi = 0; mi < 4; mi++) {
                const int m = wm * 64 + mi * 16 + gid;
                af[mi][0] = As[(m    ) * AS_STRIDE + kb + tig    ];
                af[mi][1] = As[(m + 8) * AS_STRIDE + kb + tig    ];
                af[mi][2] = As[(m    ) * AS_STRIDE + kb + tig + 4];
                af[mi][3] = As[(m + 8) * AS_STRIDE + kb + tig + 4];
            }
            #pragma unroll
            for (int ni = 0; ni < 4; ni++) {
                const int n = wn * 32 + ni * 8 + gid;
                bf[ni][0] = Bs[(kb + tig    ) * BS_STRIDE + n];
                bf[ni][1] = Bs[(kb + tig + 4) * BS_STRIDE + n];
            }
            #pragma unroll
            for (int mi = 0; mi < 4; mi++)
                #pragma unroll
                for (int ni = 0; ni < 4; ni++)
                    mma_tf32(acc[mi][ni], af[mi], bf[ni]);
        }
        __syncthreads();
    }

    // ---- epilogue: add bias, store ----
    #pragma unroll
    for (int mi = 0; mi < 4; mi++) {
        const int r = crow + wm * 64 + mi * 16 + gid;
        #pragma unroll
        for (int ni = 0; ni < 4; ni++) {
            const int c = ccol + wn * 32 + ni * 8 + 2 * tig;
            const float b0 = bias[c], b1 = bias[c + 1];
            float2 o1 = make_float2(acc[mi][ni][0] + b0, acc[mi][ni][1] + b1);
            float2 o2 = make_float2(acc[mi][ni][2] + b0, acc[mi][ni][3] + b1);
            *reinterpret_cast<float2*>(&C[(size_t)r * N + c]) = o1;
            *reinterpret_cast<float2*>(&C[(size_t)(r + 8) * N + c]) = o2;
        }
    }
}

// ---------------------------------------------------------------------------
// Attention: flash-style, one thread per query row, float4 shared reads.
// ---------------------------------------------------------------------------
#define ATT_BQ 64
#define ATT_BS 32

__global__ __launch_bounds__(ATT_BQ) void attn_kernel(
    const float* __restrict__ qkv, float* __restrict__ y)
{
    const int h   = blockIdx.y;
    const int q0  = blockIdx.x * ATT_BQ;
    const int tid = threadIdx.x;
    const float scale = 0.125f;  // 1/sqrt(64)

    __shared__ float4 Ks[ATT_BS][D_DIM / 4];
    __shared__ float4 Vs[ATT_BS][D_DIM / 4];

    float q[D_DIM], o[D_DIM];
    const float* qrow = qkv + (size_t)(q0 + tid) * QKV_N + h * D_DIM;
    #pragma unroll
    for (int d = 0; d < D_DIM; d++) {
        q[d] = qrow[d] * scale;
        o[d] = 0.0f;
    }
    float m = -INFINITY, l = 0.0f;

    const float* kbase = qkv + C_DIM     + h * D_DIM;
    const float* vbase = qkv + 2 * C_DIM + h * D_DIM;

    for (int s0 = 0; s0 < T_DIM; s0 += ATT_BS) {
        __syncthreads();
        // cooperative float4 tile load: 32 rows x 16 float4 each for K and V
        #pragma unroll
        for (int j = tid; j < ATT_BS * 16; j += ATT_BQ) {
            const int r  = j >> 4;
            const int c4 = j & 15;
            Ks[r][c4] = *reinterpret_cast<const float4*>(
                &kbase[(size_t)(s0 + r) * QKV_N + c4 * 4]);
            Vs[r][c4] = *reinterpret_cast<const float4*>(
                &vbase[(size_t)(s0 + r) * QKV_N + c4 * 4]);
        }
        __syncthreads();

        float sc[ATT_BS];
        float mt = m;
        #pragma unroll
        for (int s = 0; s < ATT_BS; s++) {
            float a0 = 0.0f, a1 = 0.0f;
            #pragma unroll
            for (int d4 = 0; d4 < 16; d4 += 2) {
                float4 k0v = Ks[s][d4];
                float4 k1v = Ks[s][d4 + 1];
                a0 += q[4 * d4 + 0] * k0v.x + q[4 * d4 + 1] * k0v.y
                    + q[4 * d4 + 2] * k0v.z + q[4 * d4 + 3] * k0v.w;
                a1 += q[4 * d4 + 4] * k1v.x + q[4 * d4 + 5] * k1v.y
                    + q[4 * d4 + 6] * k1v.z + q[4 * d4 + 7] * k1v.w;
            }
            const float a = a0 + a1;
            sc[s] = a;
            mt = fmaxf(mt, a);
        }
        const float corr = __expf(m - mt);
        m = mt;
        l *= corr;
        #pragma unroll
        for (int d = 0; d < D_DIM; d++) o[d] *= corr;
        #pragma unroll
        for (int s = 0; s < ATT_BS; s++) {
            const float p = __expf(sc[s] - m);
            l += p;
            #pragma unroll
            for (int d4 = 0; d4 < 16; d4++) {
                float4 vv = Vs[s][d4];
                o[4 * d4 + 0] += p * vv.x;
                o[4 * d4 + 1] += p * vv.y;
                o[4 * d4 + 2] += p * vv.z;
                o[4 * d4 + 3] += p * vv.w;
            }
        }
    }

    const float inv = 1.0f / l;
    float* yrow = y + (size_t)(q0 + tid) * C_DIM + h * D_DIM;
    #pragma unroll
    for (int d = 0; d < D_DIM; d++) yrow[d] = o[d] * inv;
}

// ---------------------------------------------------------------------------
// kernel_launch
// inputs: x [T,C], W_qkv [C,3C], b_qkv [3C], W_proj [C,C], b_proj [C]
// output: [T,C] float32
// ---------------------------------------------------------------------------
extern "C" void kernel_launch(void* const* d_in, const int* in_sizes, int n_in,
                              void* d_out, int out_size)
{
    const float* x      = (const float*)d_in[0];
    const float* W_qkv  = (const float*)d_in[1];
    const float* b_qkv  = (const float*)d_in[2];
    const float* W_proj = (const float*)d_in[3];
    const float* b_proj = (const float*)d_in[4];
    float* out = (float*)d_out;

    float *qkv, *y;
    cudaGetSymbolAddress((void**)&qkv, g_qkv);
    cudaGetSymbolAddress((void**)&y, g_y);

    // 1) QKV projection: [T,3C] = x @ W_qkv + b_qkv
    gemm_tf32_bias<<<dim3(QKV_N / GBN, T_DIM / GBM), 256>>>(
        T_DIM, QKV_N, C_DIM, x, W_qkv, b_qkv, qkv);

    // 2) Attention: y[T,C]
    attn_kernel<<<dim3(T_DIM / ATT_BQ, H_DIM), ATT_BQ>>>(qkv, y);

    // 3) Output projection: out = y @ W_proj + b_proj
    gemm_tf32_bias<<<dim3(C_DIM / GBN, T_DIM / GBM), 256>>>(
        T_DIM, C_DIM, C_DIM, y, W_proj, b_proj, out);
}

// round 5
// speedup vs baseline: 1.5032x; 1.0171x over previous
#include <cuda_runtime.h>
#include <cuda_bf16.h>
#include <math.h>
#include <stdint.h>

// Problem constants
#define T_DIM 2048
#define C_DIM 1024
#define H_DIM 16
#define D_DIM 64
#define QKV_N (3 * C_DIM)   // 3072

// Scratch (allocation-free: __device__ globals)
__device__ float g_qkv[T_DIM * QKV_N];   // [T, 3C]
__device__ float g_y[T_DIM * C_DIM];     // [T, C] attention output

// ---------------------------------------------------------------------------
// TF32 tensor-core GEMM: C[M,N] = A[M,K] @ B[K,N] + bias[N]
// Block tile 128x128, K-chunk 32. 8 warps (2x4), warp tile 64x32.
// ---------------------------------------------------------------------------
#define GBM 128
#define GBN 128
#define GBK 32
#define AS_STRIDE 36    // 32 + 4 pad
#define BS_STRIDE 136   // 128 + 8 pad

__device__ __forceinline__ uint32_t f2tf32(float x) {
    uint32_t r;
    asm("cvt.rna.tf32.f32 %0, %1;" : "=r"(r) : "f"(x));
    return r;
}

__device__ __forceinline__ void mma_tf32(float* d, const uint32_t* a, const uint32_t* b) {
    asm volatile(
        "mma.sync.aligned.m16n8k8.row.col.f32.tf32.tf32.f32 "
        "{%0,%1,%2,%3}, {%4,%5,%6,%7}, {%8,%9}, {%0,%1,%2,%3};"
        : "+f"(d[0]), "+f"(d[1]), "+f"(d[2]), "+f"(d[3])
        : "r"(a[0]), "r"(a[1]), "r"(a[2]), "r"(a[3]), "r"(b[0]), "r"(b[1]));
}

__global__ __launch_bounds__(256) void gemm_tf32_bias(
    int M, int N, int K,
    const float* __restrict__ A, const float* __restrict__ B,
    const float* __restrict__ bias, float* __restrict__ C)
{
    __shared__ uint32_t As[GBM * AS_STRIDE];   // [m][k]
    __shared__ uint32_t Bs[GBK * BS_STRIDE];   // [k][n]

    const int tid  = threadIdx.x;
    const int lane = tid & 31;
    const int warp = tid >> 5;
    const int gid  = lane >> 2;
    const int tig  = lane & 3;

    const int wm = warp & 1;
    const int wn = warp >> 1;

    const int crow = blockIdx.y * GBM;
    const int ccol = blockIdx.x * GBN;

    const int arow = tid >> 3;
    const int acol4 = tid & 7;
    const int brow32 = tid >> 5;
    const int bcol4 = tid & 31;

    float acc[4][4][4];
    #pragma unroll
    for (int i = 0; i < 4; i++)
        #pragma unroll
        for (int j = 0; j < 4; j++)
            #pragma unroll
            for (int r = 0; r < 4; r++) acc[i][j][r] = 0.0f;

    for (int k0 = 0; k0 < K; k0 += GBK) {
        #pragma unroll
        for (int p = 0; p < 4; p++) {
            const int r = arow + p * 32;
            float4 v = *reinterpret_cast<const float4*>(
                &A[(size_t)(crow + r) * K + k0 + acol4 * 4]);
            uint32_t* dst = &As[r * AS_STRIDE + acol4 * 4];
            dst[0] = f2tf32(v.x); dst[1] = f2tf32(v.y);
            dst[2] = f2tf32(v.z); dst[3] = f2tf32(v.w);
        }
        #pragma unroll
        for (int p = 0; p < 4; p++) {
            const int r = brow32 + p * 8;
            float4 v = *reinterpret_cast<const float4*>(
                &B[(size_t)(k0 + r) * N + ccol + bcol4 * 4]);
            uint32_t* dst = &Bs[r * BS_STRIDE + bcol4 * 4];
            dst[0] = f2tf32(v.x); dst[1] = f2tf32(v.y);
            dst[2] = f2tf32(v.z); dst[3] = f2tf32(v.w);
        }
        __syncthreads();

        #pragma unroll
        for (int kk = 0; kk < 4; kk++) {
            const int kb = kk * 8;
            uint32_t af[4][4], bf[4][2];
            #pragma unroll
            for (int mi = 0; mi < 4; mi++) {
                const int m = wm * 64 + mi * 16 + gid;
                af[mi][0] = As[(m    ) * AS_STRIDE + kb + tig    ];
                af[mi][1] = As[(m + 8) * AS_STRIDE + kb + tig    ];
                af[mi][2] = As[(m    ) * AS_STRIDE + kb + tig + 4];
                af[mi][3] = As[(m + 8) * AS_STRIDE + kb + tig + 4];
            }
            #pragma unroll
            for (int ni = 0; ni < 4; ni++) {
                const int n = wn * 32 + ni * 8 + gid;
                bf[ni][0] = Bs[(kb + tig    ) * BS_STRIDE + n];
                bf[ni][1] = Bs[(kb + tig + 4) * BS_STRIDE + n];
            }
            #pragma unroll
            for (int mi = 0; mi < 4; mi++)
                #pragma unroll
                for (int ni = 0; ni < 4; ni++)
                    mma_tf32(acc[mi][ni], af[mi], bf[ni]);
        }
        __syncthreads();
    }

    #pragma unroll
    for (int mi = 0; mi < 4; mi++) {
        const int r = crow + wm * 64 + mi * 16 + gid;
        #pragma unroll
        for (int ni = 0; ni < 4; ni++) {
            const int c = ccol + wn * 32 + ni * 8 + 2 * tig;
            const float b0 = bias[c], b1 = bias[c + 1];
            float2 o1 = make_float2(acc[mi][ni][0] + b0, acc[mi][ni][1] + b1);
            float2 o2 = make_float2(acc[mi][ni][2] + b0, acc[mi][ni][3] + b1);
            *reinterpret_cast<float2*>(&C[(size_t)r * N + c]) = o1;
            *reinterpret_cast<float2*>(&C[(size_t)(r + 8) * N + c]) = o2;
        }
    }
}

// ---------------------------------------------------------------------------
// Fast exp on the FMA/ALU pipes only (no MUFU).
// Valid for x <= 0 (clamped at -87.3). Rel err ~2e-6.
// Magic-number round-to-nearest + degree-5 poly for 2^f + exponent splice.
// ---------------------------------------------------------------------------
__device__ __forceinline__ float fast_exp(float x) {
    x = fmaxf(x, -87.3f);
    const float LOG2E = 1.4426950408889634f;
    float z = x * LOG2E;                   // in [-126, 0]
    float t = z + 12582912.0f;             // RN -> integer in mantissa
    int   n = __float_as_int(t);
    float fi = t - 12582912.0f;            // rounded integer value
    float f = z - fi;                      // frac in [-0.5, 0.5]
    float p =          1.3534543e-3f;      // ln2^5/120
    p = fmaf(p, f,     9.6178720e-3f);     // ln2^4/24
    p = fmaf(p, f,     5.5503429e-2f);     // ln2^3/6
    p = fmaf(p, f,     2.4022651e-1f);     // ln2^2/2
    p = fmaf(p, f,     6.9314718e-1f);     // ln2
    p = fmaf(p, f,     1.0f);
    // (n<<23) keeps only the integer low bits (magic's low 9 bits are 0)
    int sb = (n << 23) + 0x3F800000;
    return p * __int_as_float(sb);
}

// ---------------------------------------------------------------------------
// Attention: flash-style, one thread per query row, float4 shared reads,
// MUFU-free softmax.
// ---------------------------------------------------------------------------
#define ATT_BQ 64
#define ATT_BS 32

__global__ __launch_bounds__(ATT_BQ) void attn_kernel(
    const float* __restrict__ qkv, float* __restrict__ y)
{
    const int h   = blockIdx.y;
    const int q0  = blockIdx.x * ATT_BQ;
    const int tid = threadIdx.x;
    const float scale = 0.125f;  // 1/sqrt(64)

    __shared__ float4 Ks[ATT_BS][D_DIM / 4];
    __shared__ float4 Vs[ATT_BS][D_DIM / 4];

    float q[D_DIM], o[D_DIM];
    const float* qrow = qkv + (size_t)(q0 + tid) * QKV_N + h * D_DIM;
    #pragma unroll
    for (int d = 0; d < D_DIM; d++) {
        q[d] = qrow[d] * scale;
        o[d] = 0.0f;
    }
    float m = -INFINITY, l = 0.0f;

    const float* kbase = qkv + C_DIM     + h * D_DIM;
    const float* vbase = qkv + 2 * C_DIM + h * D_DIM;

    for (int s0 = 0; s0 < T_DIM; s0 += ATT_BS) {
        __syncthreads();
        #pragma unroll
        for (int j = tid; j < ATT_BS * 16; j += ATT_BQ) {
            const int r  = j >> 4;
            const int c4 = j & 15;
            Ks[r][c4] = *reinterpret_cast<const float4*>(
                &kbase[(size_t)(s0 + r) * QKV_N + c4 * 4]);
            Vs[r][c4] = *reinterpret_cast<const float4*>(
                &vbase[(size_t)(s0 + r) * QKV_N + c4 * 4]);
        }
        __syncthreads();

        float sc[ATT_BS];
        float mt = m;
        #pragma unroll
        for (int s = 0; s < ATT_BS; s++) {
            float a0 = 0.0f, a1 = 0.0f;
            #pragma unroll
            for (int d4 = 0; d4 < 16; d4 += 2) {
                float4 k0v = Ks[s][d4];
                float4 k1v = Ks[s][d4 + 1];
                a0 += q[4 * d4 + 0] * k0v.x + q[4 * d4 + 1] * k0v.y
                    + q[4 * d4 + 2] * k0v.z + q[4 * d4 + 3] * k0v.w;
                a1 += q[4 * d4 + 4] * k1v.x + q[4 * d4 + 5] * k1v.y
                    + q[4 * d4 + 6] * k1v.z + q[4 * d4 + 7] * k1v.w;
            }
            const float a = a0 + a1;
            sc[s] = a;
            mt = fmaxf(mt, a);
        }
        const float corr = fast_exp(m - mt);
        m = mt;
        l *= corr;
        #pragma unroll
        for (int d = 0; d < D_DIM; d++) o[d] *= corr;
        #pragma unroll
        for (int s = 0; s < ATT_BS; s++) {
            const float p = fast_exp(sc[s] - m);
            l += p;
            #pragma unroll
            for (int d4 = 0; d4 < 16; d4++) {
                float4 vv = Vs[s][d4];
                o[4 * d4 + 0] += p * vv.x;
                o[4 * d4 + 1] += p * vv.y;
                o[4 * d4 + 2] += p * vv.z;
                o[4 * d4 + 3] += p * vv.w;
            }
        }
    }

    const float inv = 1.0f / l;
    float* yrow = y + (size_t)(q0 + tid) * C_DIM + h * D_DIM;
    #pragma unroll
    for (int d = 0; d < D_DIM; d++) yrow[d] = o[d] * inv;
}

// ---------------------------------------------------------------------------
// kernel_launch
// inputs: x [T,C], W_qkv [C,3C], b_qkv [3C], W_proj [C,C], b_proj [C]
// output: [T,C] float32
// ---------------------------------------------------------------------------
extern "C" void kernel_launch(void* const* d_in, const int* in_sizes, int n_in,
                              void* d_out, int out_size)
{
    const float* x      = (const float*)d_in[0];
    const float* W_qkv  = (const float*)d_in[1];
    const float* b_qkv  = (const float*)d_in[2];
    const float* W_proj = (const float*)d_in[3];
    const float* b_proj = (const float*)d_in[4];
    float* out = (float*)d_out;

    float *qkv, *y;
    cudaGetSymbolAddress((void**)&qkv, g_qkv);
    cudaGetSymbolAddress((void**)&y, g_y);

    gemm_tf32_bias<<<dim3(QKV_N / GBN, T_DIM / GBM), 256>>>(
        T_DIM, QKV_N, C_DIM, x, W_qkv, b_qkv, qkv);

    attn_kernel<<<dim3(T_DIM / ATT_BQ, H_DIM), ATT_BQ>>>(qkv, y);

    gemm_tf32_bias<<<dim3(C_DIM / GBN, T_DIM / GBM), 256>>>(
        T_DIM, C_DIM, C_DIM, y, W_proj, b_proj, out);
}

// round 6
// speedup vs baseline: 3.0912x; 2.0564x over previous
#include <cuda_runtime.h>
#include <cuda_bf16.h>
#include <math.h>
#include <stdint.h>

// Problem constants
#define T_DIM 2048
#define C_DIM 1024
#define H_DIM 16
#define D_DIM 64
#define QKV_N (3 * C_DIM)   // 3072

// Scratch (allocation-free: __device__ globals)
__device__ float g_qkv[T_DIM * QKV_N];   // [T, 3C]
__device__ float g_y[T_DIM * C_DIM];     // [T, C] attention output

__device__ __forceinline__ uint32_t f2tf32(float x) {
    uint32_t r;
    asm("cvt.rna.tf32.f32 %0, %1;" : "=r"(r) : "f"(x));
    return r;
}

__device__ __forceinline__ void mma_tf32(float* d, const uint32_t* a, const uint32_t* b) {
    asm volatile(
        "mma.sync.aligned.m16n8k8.row.col.f32.tf32.tf32.f32 "
        "{%0,%1,%2,%3}, {%4,%5,%6,%7}, {%8,%9}, {%0,%1,%2,%3};"
        : "+f"(d[0]), "+f"(d[1]), "+f"(d[2]), "+f"(d[3])
        : "r"(a[0]), "r"(a[1]), "r"(a[2]), "r"(a[3]), "r"(b[0]), "r"(b[1]));
}

// ---------------------------------------------------------------------------
// TF32 tensor-core GEMM: C[M,N] = A[M,K] @ B[K,N] + bias[N]
// ---------------------------------------------------------------------------
#define GBM 128
#define GBN 128
#define GBK 32
#define AS_STRIDE 36
#define BS_STRIDE 136

__global__ __launch_bounds__(256) void gemm_tf32_bias(
    int M, int N, int K,
    const float* __restrict__ A, const float* __restrict__ B,
    const float* __restrict__ bias, float* __restrict__ C)
{
    __shared__ uint32_t As[GBM * AS_STRIDE];
    __shared__ uint32_t Bs[GBK * BS_STRIDE];

    const int tid  = threadIdx.x;
    const int lane = tid & 31;
    const int warp = tid >> 5;
    const int gid  = lane >> 2;
    const int tig  = lane & 3;

    const int wm = warp & 1;
    const int wn = warp >> 1;

    const int crow = blockIdx.y * GBM;
    const int ccol = blockIdx.x * GBN;

    const int arow = tid >> 3;
    const int acol4 = tid & 7;
    const int brow32 = tid >> 5;
    const int bcol4 = tid & 31;

    float acc[4][4][4];
    #pragma unroll
    for (int i = 0; i < 4; i++)
        #pragma unroll
        for (int j = 0; j < 4; j++)
            #pragma unroll
            for (int r = 0; r < 4; r++) acc[i][j][r] = 0.0f;

    for (int k0 = 0; k0 < K; k0 += GBK) {
        #pragma unroll
        for (int p = 0; p < 4; p++) {
            const int r = arow + p * 32;
            float4 v = *reinterpret_cast<const float4*>(
                &A[(size_t)(crow + r) * K + k0 + acol4 * 4]);
            uint32_t* dst = &As[r * AS_STRIDE + acol4 * 4];
            dst[0] = f2tf32(v.x); dst[1] = f2tf32(v.y);
            dst[2] = f2tf32(v.z); dst[3] = f2tf32(v.w);
        }
        #pragma unroll
        for (int p = 0; p < 4; p++) {
            const int r = brow32 + p * 8;
            float4 v = *reinterpret_cast<const float4*>(
                &B[(size_t)(k0 + r) * N + ccol + bcol4 * 4]);
            uint32_t* dst = &Bs[r * BS_STRIDE + bcol4 * 4];
            dst[0] = f2tf32(v.x); dst[1] = f2tf32(v.y);
            dst[2] = f2tf32(v.z); dst[3] = f2tf32(v.w);
        }
        __syncthreads();

        #pragma unroll
        for (int kk = 0; kk < 4; kk++) {
            const int kb = kk * 8;
            uint32_t af[4][4], bf[4][2];
            #pragma unroll
            for (int mi = 0; mi < 4; mi++) {
                const int m = wm * 64 + mi * 16 + gid;
                af[mi][0] = As[(m    ) * AS_STRIDE + kb + tig    ];
                af[mi][1] = As[(m + 8) * AS_STRIDE + kb + tig    ];
                af[mi][2] = As[(m    ) * AS_STRIDE + kb + tig + 4];
                af[mi][3] = As[(m + 8) * AS_STRIDE + kb + tig + 4];
            }
            #pragma unroll
            for (int ni = 0; ni < 4; ni++) {
                const int n = wn * 32 + ni * 8 + gid;
                bf[ni][0] = Bs[(kb + tig    ) * BS_STRIDE + n];
                bf[ni][1] = Bs[(kb + tig + 4) * BS_STRIDE + n];
            }
            #pragma unroll
            for (int mi = 0; mi < 4; mi++)
                #pragma unroll
                for (int ni = 0; ni < 4; ni++)
                    mma_tf32(acc[mi][ni], af[mi], bf[ni]);
        }
        __syncthreads();
    }

    #pragma unroll
    for (int mi = 0; mi < 4; mi++) {
        const int r = crow + wm * 64 + mi * 16 + gid;
        #pragma unroll
        for (int ni = 0; ni < 4; ni++) {
            const int c = ccol + wn * 32 + ni * 8 + 2 * tig;
            const float b0 = bias[c], b1 = bias[c + 1];
            float2 o1 = make_float2(acc[mi][ni][0] + b0, acc[mi][ni][1] + b1);
            float2 o2 = make_float2(acc[mi][ni][2] + b0, acc[mi][ni][3] + b1);
            *reinterpret_cast<float2*>(&C[(size_t)r * N + c]) = o1;
            *reinterpret_cast<float2*>(&C[(size_t)(r + 8) * N + c]) = o2;
        }
    }
}

// ---------------------------------------------------------------------------
// Fast exp on FMA/ALU pipes only. Valid for x <= 0 (clamped). Rel err ~2e-6.
// ---------------------------------------------------------------------------
__device__ __forceinline__ float fast_exp(float x) {
    x = fmaxf(x, -87.3f);
    float z = x * 1.4426950408889634f;
    float t = z + 12582912.0f;
    int   n = __float_as_int(t);
    float fi = t - 12582912.0f;
    float f = z - fi;
    float p =          1.3534543e-3f;
    p = fmaf(p, f,     9.6178720e-3f);
    p = fmaf(p, f,     5.5503429e-2f);
    p = fmaf(p, f,     2.4022651e-1f);
    p = fmaf(p, f,     6.9314718e-1f);
    p = fmaf(p, f,     1.0f);
    int sb = (n << 23) + 0x3F800000;
    return p * __int_as_float(sb);
}

// ---------------------------------------------------------------------------
// Tensor-core flash attention.
// Block: 256 threads = 8 warps as 4(m) x 2(n). Q tile 128 rows x D=64 held as
// persistent tf32 A-fragments. Loop over S-tiles of 64 keys:
//   S = Q@K^T (mma) -> smem -> online softmax (smem) -> P@V^T (mma) into O.
// Smem: S[128][68], Ks[64][68], Vt[64][68], m/l/corr[128].
// ---------------------------------------------------------------------------
#define FA_M 128
#define FA_S 64
#define SSTR 68
#define ATTN_SMEM ((128 * SSTR + 64 * SSTR + 64 * SSTR + 3 * 128) * 4)

__global__ __launch_bounds__(256) void attn_tc(
    const float* __restrict__ qkv, float* __restrict__ y)
{
    extern __shared__ float sm[];
    float* S    = sm;                    // [128][SSTR]
    float* Ks   = sm + 128 * SSTR;       // [64][SSTR]
    float* Vt   = Ks + 64 * SSTR;        // [64][SSTR]  (Vt[d][s])
    float* Mrow = Vt + 64 * SSTR;        // [128]
    float* Lrow = Mrow + 128;            // [128]
    float* Crow = Lrow + 128;            // [128]

    const int h  = blockIdx.y;
    const int q0 = blockIdx.x * FA_M;
    const int tid  = threadIdx.x;
    const int lane = tid & 31;
    const int warp = tid >> 5;
    const int gid  = lane >> 2;
    const int tig  = lane & 3;
    const int wm   = warp & 3;    // 0..3 -> 32 m-rows each
    const int wn   = warp >> 2;   // 0..1 -> 32 n-cols each

    const float* qbase = qkv + h * D_DIM;
    const float* kbase = qkv + C_DIM + h * D_DIM;
    const float* vbase = qkv + 2 * C_DIM + h * D_DIM;

    // ---- stage Q tile into S (tf32-rounded, pre-scaled by 1/8) ----
    for (int i = tid; i < FA_M * 16; i += 256) {
        const int r  = i >> 4;
        const int c4 = i & 15;
        float4 v = *reinterpret_cast<const float4*>(
            &qbase[(size_t)(q0 + r) * QKV_N + c4 * 4]);
        float* dst = &S[r * SSTR + c4 * 4];
        dst[0] = __int_as_float(f2tf32(v.x * 0.125f));
        dst[1] = __int_as_float(f2tf32(v.y * 0.125f));
        dst[2] = __int_as_float(f2tf32(v.z * 0.125f));
        dst[3] = __int_as_float(f2tf32(v.w * 0.125f));
    }
    if (tid < FA_M) { Mrow[tid] = -1e30f; Lrow[tid] = 0.0f; }
    __syncthreads();

    // ---- load persistent Q fragments ----
    uint32_t qf[2][8][4];
    #pragma unroll
    for (int mi = 0; mi < 2; mi++) {
        const int m = wm * 32 + mi * 16 + gid;
        #pragma unroll
        for (int kk = 0; kk < 8; kk++) {
            const int kb = kk * 8;
            qf[mi][kk][0] = __float_as_uint(S[(m    ) * SSTR + kb + tig    ]);
            qf[mi][kk][1] = __float_as_uint(S[(m + 8) * SSTR + kb + tig    ]);
            qf[mi][kk][2] = __float_as_uint(S[(m    ) * SSTR + kb + tig + 4]);
            qf[mi][kk][3] = __float_as_uint(S[(m + 8) * SSTR + kb + tig + 4]);
        }
    }

    float oacc[2][4][4];
    #pragma unroll
    for (int mi = 0; mi < 2; mi++)
        #pragma unroll
        for (int ni = 0; ni < 4; ni++)
            #pragma unroll
            for (int r = 0; r < 4; r++) oacc[mi][ni][r] = 0.0f;

    for (int s0 = 0; s0 < T_DIM; s0 += FA_S) {
        __syncthreads();   // prev-iter frag reads / Q-frag loads done

        // ---- load K tile [64][64] and V tile transposed Vt[d][s] ----
        for (int i = tid; i < FA_S * 16; i += 256) {
            const int r  = i >> 4;
            const int c4 = i & 15;
            float4 kv = *reinterpret_cast<const float4*>(
                &kbase[(size_t)(s0 + r) * QKV_N + c4 * 4]);
            float* kd = &Ks[r * SSTR + c4 * 4];
            kd[0] = __int_as_float(f2tf32(kv.x));
            kd[1] = __int_as_float(f2tf32(kv.y));
            kd[2] = __int_as_float(f2tf32(kv.z));
            kd[3] = __int_as_float(f2tf32(kv.w));
            float4 vv = *reinterpret_cast<const float4*>(
                &vbase[(size_t)(s0 + r) * QKV_N + c4 * 4]);
            float ve[4] = {vv.x, vv.y, vv.z, vv.w};
            const int d0 = c4 * 4;
            #pragma unroll
            for (int j = 0; j < 4; j++) {        // rotated to cut STS conflicts
                const int ii = (j + c4) & 3;
                Vt[(d0 + ii) * SSTR + r] = __int_as_float(f2tf32(ve[ii]));
            }
        }
        __syncthreads();

        // ---- S = Q @ K^T  (M=128, N=64, K=64) ----
        float sacc[2][4][4];
        #pragma unroll
        for (int mi = 0; mi < 2; mi++)
            #pragma unroll
            for (int ni = 0; ni < 4; ni++)
                #pragma unroll
                for (int r = 0; r < 4; r++) sacc[mi][ni][r] = 0.0f;

        #pragma unroll
        for (int kk = 0; kk < 8; kk++) {
            const int kb = kk * 8;
            uint32_t bf[4][2];
            #pragma unroll
            for (int ni = 0; ni < 4; ni++) {
                const int n = wn * 32 + ni * 8 + gid;   // key row
                bf[ni][0] = __float_as_uint(Ks[n * SSTR + kb + tig    ]);
                bf[ni][1] = __float_as_uint(Ks[n * SSTR + kb + tig + 4]);
            }
            #pragma unroll
            for (int mi = 0; mi < 2; mi++)
                #pragma unroll
                for (int ni = 0; ni < 4; ni++)
                    mma_tf32(sacc[mi][ni], qf[mi][kk], bf[ni]);
        }
        // write scores to smem
        #pragma unroll
        for (int mi = 0; mi < 2; mi++) {
            const int m = wm * 32 + mi * 16 + gid;
            #pragma unroll
            for (int ni = 0; ni < 4; ni++) {
                const int n = wn * 32 + ni * 8 + 2 * tig;
                *reinterpret_cast<float2*>(&S[m * SSTR + n]) =
                    make_float2(sacc[mi][ni][0], sacc[mi][ni][1]);
                *reinterpret_cast<float2*>(&S[(m + 8) * SSTR + n]) =
                    make_float2(sacc[mi][ni][2], sacc[mi][ni][3]);
            }
        }
        __syncthreads();

        // ---- online softmax: 2 threads per row, 32 cols each ----
        {
            const int row = tid >> 1;
            const int c0  = (tid & 1) * 32;
            const float mold = Mrow[row];
            const float lold = Lrow[row];
            float vc[32];
            float mx = -1e30f;
            #pragma unroll
            for (int j = 0; j < 32; j++) {
                vc[j] = S[row * SSTR + c0 + j];
                mx = fmaxf(mx, vc[j]);
            }
            mx = fmaxf(mx, __shfl_xor_sync(0xffffffff, mx, 1));
            const float mnew = fmaxf(mold, mx);
            const float corr = fast_exp(mold - mnew);
            float lsum = 0.0f;
            #pragma unroll
            for (int j = 0; j < 32; j++) {
                const float p = fast_exp(vc[j] - mnew);
                lsum += p;
                S[row * SSTR + c0 + j] = __int_as_float(f2tf32(p));
            }
            lsum += __shfl_xor_sync(0xffffffff, lsum, 1);
            if (!(tid & 1)) {
                Mrow[row] = mnew;
                Lrow[row] = lold * corr + lsum;
                Crow[row] = corr;
            }
        }
        __syncthreads();

        // ---- rescale O and accumulate P @ V ----
        #pragma unroll
        for (int mi = 0; mi < 2; mi++) {
            const int m = wm * 32 + mi * 16 + gid;
            const float c1 = Crow[m], c2 = Crow[m + 8];
            #pragma unroll
            for (int ni = 0; ni < 4; ni++) {
                oacc[mi][ni][0] *= c1; oacc[mi][ni][1] *= c1;
                oacc[mi][ni][2] *= c2; oacc[mi][ni][3] *= c2;
            }
        }
        #pragma unroll
        for (int kk = 0; kk < 8; kk++) {
            const int kb = kk * 8;          // s-dim chunk
            uint32_t af[2][4], bf[4][2];
            #pragma unroll
            for (int mi = 0; mi < 2; mi++) {
                const int m = wm * 32 + mi * 16 + gid;
                af[mi][0] = __float_as_uint(S[(m    ) * SSTR + kb + tig    ]);
                af[mi][1] = __float_as_uint(S[(m + 8) * SSTR + kb + tig    ]);
                af[mi][2] = __float_as_uint(S[(m    ) * SSTR + kb + tig + 4]);
                af[mi][3] = __float_as_uint(S[(m + 8) * SSTR + kb + tig + 4]);
            }
            #pragma unroll
            for (int ni = 0; ni < 4; ni++) {
                const int n = wn * 32 + ni * 8 + gid;   // d-col
                bf[ni][0] = __float_as_uint(Vt[n * SSTR + kb + tig    ]);
                bf[ni][1] = __float_as_uint(Vt[n * SSTR + kb + tig + 4]);
            }
            #pragma unroll
            for (int mi = 0; mi < 2; mi++)
                #pragma unroll
                for (int ni = 0; ni < 4; ni++)
                    mma_tf32(oacc[mi][ni], af[mi], bf[ni]);
        }
    }
    __syncthreads();

    // ---- epilogue: normalize by l, store ----
    #pragma unroll
    for (int mi = 0; mi < 2; mi++) {
        const int m = wm * 32 + mi * 16 + gid;
        const float il1 = 1.0f / Lrow[m];
        const float il2 = 1.0f / Lrow[m + 8];
        #pragma unroll
        for (int ni = 0; ni < 4; ni++) {
            const int n = wn * 32 + ni * 8 + 2 * tig;
            float* y1 = &y[(size_t)(q0 + m) * C_DIM + h * D_DIM + n];
            float* y2 = &y[(size_t)(q0 + m + 8) * C_DIM + h * D_DIM + n];
            *reinterpret_cast<float2*>(y1) =
                make_float2(oacc[mi][ni][0] * il1, oacc[mi][ni][1] * il1);
            *reinterpret_cast<float2*>(y2) =
                make_float2(oacc[mi][ni][2] * il2, oacc[mi][ni][3] * il2);
        }
    }
}

// ---------------------------------------------------------------------------
// kernel_launch
// ---------------------------------------------------------------------------
extern "C" void kernel_launch(void* const* d_in, const int* in_sizes, int n_in,
                              void* d_out, int out_size)
{
    const float* x      = (const float*)d_in[0];
    const float* W_qkv  = (const float*)d_in[1];
    const float* b_qkv  = (const float*)d_in[2];
    const float* W_proj = (const float*)d_in[3];
    const float* b_proj = (const float*)d_in[4];
    float* out = (float*)d_out;

    float *qkv, *y;
    cudaGetSymbolAddress((void**)&qkv, g_qkv);
    cudaGetSymbolAddress((void**)&y, g_y);

    cudaFuncSetAttribute(attn_tc,
        cudaFuncAttributeMaxDynamicSharedMemorySize, ATTN_SMEM);

    gemm_tf32_bias<<<dim3(QKV_N / GBN, T_DIM / GBM), 256>>>(
        T_DIM, QKV_N, C_DIM, x, W_qkv, b_qkv, qkv);

    attn_tc<<<dim3(T_DIM / FA_M, H_DIM), 256, ATTN_SMEM>>>(qkv, y);

    gemm_tf32_bias<<<dim3(C_DIM / GBN, T_DIM / GBM), 256>>>(
        T_DIM, C_DIM, C_DIM, y, W_proj, b_proj, out);
}

// round 7
// speedup vs baseline: 3.3801x; 1.0934x over previous
#include <cuda_runtime.h>
#include <cuda_bf16.h>
#include <math.h>
#include <stdint.h>

// Problem constants
#define T_DIM 2048
#define C_DIM 1024
#define H_DIM 16
#define D_DIM 64
#define QKV_N (3 * C_DIM)   // 3072

// Scratch (allocation-free: __device__ globals)
__device__ float g_qkv[T_DIM * QKV_N];   // [T, 3C]
__device__ float g_y[T_DIM * C_DIM];     // [T, C] attention output

__device__ __forceinline__ uint32_t f2tf32(float x) {
    uint32_t r;
    asm("cvt.rna.tf32.f32 %0, %1;" : "=r"(r) : "f"(x));
    return r;
}

__device__ __forceinline__ void mma_tf32(float* d, const uint32_t* a, const uint32_t* b) {
    asm volatile(
        "mma.sync.aligned.m16n8k8.row.col.f32.tf32.tf32.f32 "
        "{%0,%1,%2,%3}, {%4,%5,%6,%7}, {%8,%9}, {%0,%1,%2,%3};"
        : "+f"(d[0]), "+f"(d[1]), "+f"(d[2]), "+f"(d[3])
        : "r"(a[0]), "r"(a[1]), "r"(a[2]), "r"(a[3]), "r"(b[0]), "r"(b[1]));
}

// ---------------------------------------------------------------------------
// TF32 tensor-core GEMM, double-buffered smem + register prefetch.
// C[M,N] = A[M,K] @ B[K,N] + bias[N]
// ---------------------------------------------------------------------------
#define GBM 128
#define GBN 128
#define GBK 32
#define AS_STRIDE 36
#define BS_STRIDE 136
#define AS_WORDS (GBM * AS_STRIDE)
#define BS_WORDS (GBK * BS_STRIDE)
#define GEMM_SMEM ((2 * AS_WORDS + 2 * BS_WORDS) * 4)

__global__ __launch_bounds__(256) void gemm_tf32_bias(
    int M, int N, int K,
    const float* __restrict__ A, const float* __restrict__ B,
    const float* __restrict__ bias, float* __restrict__ C)
{
    extern __shared__ uint32_t gsm[];
    uint32_t* AsBase = gsm;                    // 2 buffers
    uint32_t* BsBase = gsm + 2 * AS_WORDS;     // 2 buffers

    const int tid  = threadIdx.x;
    const int lane = tid & 31;
    const int warp = tid >> 5;
    const int gid  = lane >> 2;
    const int tig  = lane & 3;

    const int wm = warp & 1;
    const int wn = warp >> 1;

    const int crow = blockIdx.y * GBM;
    const int ccol = blockIdx.x * GBN;

    const int arow  = tid >> 3;
    const int acol4 = tid & 7;
    const int brow32 = tid >> 5;
    const int bcol4  = tid & 31;

    float acc[4][4][4];
    #pragma unroll
    for (int i = 0; i < 4; i++)
        #pragma unroll
        for (int j = 0; j < 4; j++)
            #pragma unroll
            for (int r = 0; r < 4; r++) acc[i][j][r] = 0.0f;

    float4 aR[4], bR[4];

    // prologue: load tile k0=0
    #pragma unroll
    for (int p = 0; p < 4; p++) {
        aR[p] = *reinterpret_cast<const float4*>(
            &A[(size_t)(crow + arow + p * 32) * K + acol4 * 4]);
        bR[p] = *reinterpret_cast<const float4*>(
            &B[(size_t)(brow32 + p * 8) * N + ccol + bcol4 * 4]);
    }
    {
        uint32_t* As = AsBase;
        uint32_t* Bs = BsBase;
        #pragma unroll
        for (int p = 0; p < 4; p++) {
            uint32_t* da = &As[(arow + p * 32) * AS_STRIDE + acol4 * 4];
            da[0] = f2tf32(aR[p].x); da[1] = f2tf32(aR[p].y);
            da[2] = f2tf32(aR[p].z); da[3] = f2tf32(aR[p].w);
            uint32_t* db = &Bs[(brow32 + p * 8) * BS_STRIDE + bcol4 * 4];
            db[0] = f2tf32(bR[p].x); db[1] = f2tf32(bR[p].y);
            db[2] = f2tf32(bR[p].z); db[3] = f2tf32(bR[p].w);
        }
    }
    __syncthreads();

    int buf = 0;
    for (int k0 = 0; k0 < K; k0 += GBK) {
        const bool has_next = (k0 + GBK < K);
        if (has_next) {
            const int kn = k0 + GBK;
            #pragma unroll
            for (int p = 0; p < 4; p++) {
                aR[p] = *reinterpret_cast<const float4*>(
                    &A[(size_t)(crow + arow + p * 32) * K + kn + acol4 * 4]);
                bR[p] = *reinterpret_cast<const float4*>(
                    &B[(size_t)(kn + brow32 + p * 8) * N + ccol + bcol4 * 4]);
            }
        }

        uint32_t* As = AsBase + buf * AS_WORDS;
        uint32_t* Bs = BsBase + buf * BS_WORDS;
        #pragma unroll
        for (int kk = 0; kk < 4; kk++) {
            const int kb = kk * 8;
            uint32_t af[4][4], bf[4][2];
            #pragma unroll
            for (int mi = 0; mi < 4; mi++) {
                const int m = wm * 64 + mi * 16 + gid;
                af[mi][0] = As[(m    ) * AS_STRIDE + kb + tig    ];
                af[mi][1] = As[(m + 8) * AS_STRIDE + kb + tig    ];
                af[mi][2] = As[(m    ) * AS_STRIDE + kb + tig + 4];
                af[mi][3] = As[(m + 8) * AS_STRIDE + kb + tig + 4];
            }
            #pragma unroll
            for (int ni = 0; ni < 4; ni++) {
                const int n = wn * 32 + ni * 8 + gid;
                bf[ni][0] = Bs[(kb + tig    ) * BS_STRIDE + n];
                bf[ni][1] = Bs[(kb + tig + 4) * BS_STRIDE + n];
            }
            #pragma unroll
            for (int mi = 0; mi < 4; mi++)
                #pragma unroll
                for (int ni = 0; ni < 4; ni++)
                    mma_tf32(acc[mi][ni], af[mi], bf[ni]);
        }

        if (has_next) {
            uint32_t* Asn = AsBase + (buf ^ 1) * AS_WORDS;
            uint32_t* Bsn = BsBase + (buf ^ 1) * BS_WORDS;
            #pragma unroll
            for (int p = 0; p < 4; p++) {
                uint32_t* da = &Asn[(arow + p * 32) * AS_STRIDE + acol4 * 4];
                da[0] = f2tf32(aR[p].x); da[1] = f2tf32(aR[p].y);
                da[2] = f2tf32(aR[p].z); da[3] = f2tf32(aR[p].w);
                uint32_t* db = &Bsn[(brow32 + p * 8) * BS_STRIDE + bcol4 * 4];
                db[0] = f2tf32(bR[p].x); db[1] = f2tf32(bR[p].y);
                db[2] = f2tf32(bR[p].z); db[3] = f2tf32(bR[p].w);
            }
            __syncthreads();
            buf ^= 1;
        }
    }

    #pragma unroll
    for (int mi = 0; mi < 4; mi++) {
        const int r = crow + wm * 64 + mi * 16 + gid;
        #pragma unroll
        for (int ni = 0; ni < 4; ni++) {
            const int c = ccol + wn * 32 + ni * 8 + 2 * tig;
            const float b0 = bias[c], b1 = bias[c + 1];
            float2 o1 = make_float2(acc[mi][ni][0] + b0, acc[mi][ni][1] + b1);
            float2 o2 = make_float2(acc[mi][ni][2] + b0, acc[mi][ni][3] + b1);
            *reinterpret_cast<float2*>(&C[(size_t)r * N + c]) = o1;
            *reinterpret_cast<float2*>(&C[(size_t)(r + 8) * N + c]) = o2;
        }
    }
}

// ---------------------------------------------------------------------------
// Fast exp on FMA/ALU pipes only. Valid for x <= 0 (clamped). Rel err ~2e-6.
// ---------------------------------------------------------------------------
__device__ __forceinline__ float fast_exp(float x) {
    x = fmaxf(x, -87.3f);
    float z = x * 1.4426950408889634f;
    float t = z + 12582912.0f;
    int   n = __float_as_int(t);
    float fi = t - 12582912.0f;
    float f = z - fi;
    float p =          1.3534543e-3f;
    p = fmaf(p, f,     9.6178720e-3f);
    p = fmaf(p, f,     5.5503429e-2f);
    p = fmaf(p, f,     2.4022651e-1f);
    p = fmaf(p, f,     6.9314718e-1f);
    p = fmaf(p, f,     1.0f);
    int sb = (n << 23) + 0x3F800000;
    return p * __int_as_float(sb);
}

// ---------------------------------------------------------------------------
// Tensor-core flash attention, register-resident online softmax.
// Block: 256 threads = 8 warps as 4(m) x 2(n). Q tile 128 x 64 persistent
// tf32 A-fragments. Per 64-key tile:
//   S = Q@K^T (mma, regs) -> softmax on C-fragments (shfl + tiny smem
//   partials) -> P (tf32) to smem -> P@V^T (mma) into O fragments.
// ---------------------------------------------------------------------------
#define FA_M 128
#define FA_S 64
#define SSTR 68
// S[128][SSTR] + Ks[64][SSTR] + Vt[64][SSTR] + Pmx[128][2] + Psm[128][2]
#define ATTN_SMEM ((128 * SSTR + 64 * SSTR + 64 * SSTR + 2 * 128 + 2 * 128) * 4)

__global__ __launch_bounds__(256) void attn_tc(
    const float* __restrict__ qkv, float* __restrict__ y)
{
    extern __shared__ float sm[];
    float* S    = sm;                    // [128][SSTR]  (Q staging, then P)
    float* Ks   = sm + 128 * SSTR;       // [64][SSTR]
    float* Vt   = Ks + 64 * SSTR;        // [64][SSTR]  (Vt[d][s])
    float* Pmx  = Vt + 64 * SSTR;        // [128][2]
    float* Psm  = Pmx + 2 * 128;         // [128][2]

    const int h  = blockIdx.y;
    const int q0 = blockIdx.x * FA_M;
    const int tid  = threadIdx.x;
    const int lane = tid & 31;
    const int warp = tid >> 5;
    const int gid  = lane >> 2;
    const int tig  = lane & 3;
    const int wm   = warp & 3;    // 0..3 -> 32 m-rows each
    const int wn   = warp >> 2;   // 0..1 -> 32 n-cols each

    const float* qbase = qkv + h * D_DIM;
    const float* kbase = qkv + C_DIM + h * D_DIM;
    const float* vbase = qkv + 2 * C_DIM + h * D_DIM;

    // ---- stage Q tile into S (tf32-rounded, pre-scaled by 1/8) ----
    for (int i = tid; i < FA_M * 16; i += 256) {
        const int r  = i >> 4;
        const int c4 = i & 15;
        float4 v = *reinterpret_cast<const float4*>(
            &qbase[(size_t)(q0 + r) * QKV_N + c4 * 4]);
        float* dst = &S[r * SSTR + c4 * 4];
        dst[0] = __int_as_float(f2tf32(v.x * 0.125f));
        dst[1] = __int_as_float(f2tf32(v.y * 0.125f));
        dst[2] = __int_as_float(f2tf32(v.z * 0.125f));
        dst[3] = __int_as_float(f2tf32(v.w * 0.125f));
    }
    __syncthreads();

    // ---- load persistent Q fragments ----
    uint32_t qf[2][8][4];
    #pragma unroll
    for (int mi = 0; mi < 2; mi++) {
        const int m = wm * 32 + mi * 16 + gid;
        #pragma unroll
        for (int kk = 0; kk < 8; kk++) {
            const int kb = kk * 8;
            qf[mi][kk][0] = __float_as_uint(S[(m    ) * SSTR + kb + tig    ]);
            qf[mi][kk][1] = __float_as_uint(S[(m + 8) * SSTR + kb + tig    ]);
            qf[mi][kk][2] = __float_as_uint(S[(m    ) * SSTR + kb + tig + 4]);
            qf[mi][kk][3] = __float_as_uint(S[(m + 8) * SSTR + kb + tig + 4]);
        }
    }

    float oacc[2][4][4];
    #pragma unroll
    for (int mi = 0; mi < 2; mi++)
        #pragma unroll
        for (int ni = 0; ni < 4; ni++)
            #pragma unroll
            for (int r = 0; r < 4; r++) oacc[mi][ni][r] = 0.0f;

    // running row stats in registers; index [mi*2+half] -> row wm*32+mi*16+half*8+gid
    float mrun[4] = {-1e30f, -1e30f, -1e30f, -1e30f};
    float lrun[4] = {0.0f, 0.0f, 0.0f, 0.0f};

    for (int s0 = 0; s0 < T_DIM; s0 += FA_S) {
        __syncthreads();   // prev-iter PV frag reads (S, Vt) done; Q frags loaded

        // ---- stage K tile [64][64] and V transposed Vt[d][s] ----
        for (int i = tid; i < FA_S * 16; i += 256) {
            const int r  = i >> 4;
            const int c4 = i & 15;
            float4 kv = *reinterpret_cast<const float4*>(
                &kbase[(size_t)(s0 + r) * QKV_N + c4 * 4]);
            float* kd = &Ks[r * SSTR + c4 * 4];
            kd[0] = __int_as_float(f2tf32(kv.x));
            kd[1] = __int_as_float(f2tf32(kv.y));
            kd[2] = __int_as_float(f2tf32(kv.z));
            kd[3] = __int_as_float(f2tf32(kv.w));
            float4 vv = *reinterpret_cast<const float4*>(
                &vbase[(size_t)(s0 + r) * QKV_N + c4 * 4]);
            float ve[4] = {vv.x, vv.y, vv.z, vv.w};
            const int d0 = c4 * 4;
            #pragma unroll
            for (int j = 0; j < 4; j++) {        // rotated to cut STS conflicts
                const int ii = (j + c4) & 3;
                Vt[(d0 + ii) * SSTR + r] = __int_as_float(f2tf32(ve[ii]));
            }
        }
        __syncthreads();

        // ---- S = Q @ K^T  (M=128, N=64, K=64), accumulators in regs ----
        float sacc[2][4][4];
        #pragma unroll
        for (int mi = 0; mi < 2; mi++)
            #pragma unroll
            for (int ni = 0; ni < 4; ni++)
                #pragma unroll
                for (int r = 0; r < 4; r++) sacc[mi][ni][r] = 0.0f;

        #pragma unroll
        for (int kk = 0; kk < 8; kk++) {
            const int kb = kk * 8;
            uint32_t bf[4][2];
            #pragma unroll
            for (int ni = 0; ni < 4; ni++) {
                const int n = wn * 32 + ni * 8 + gid;   // key row
                bf[ni][0] = __float_as_uint(Ks[n * SSTR + kb + tig    ]);
                bf[ni][1] = __float_as_uint(Ks[n * SSTR + kb + tig + 4]);
            }
            #pragma unroll
            for (int mi = 0; mi < 2; mi++)
                #pragma unroll
                for (int ni = 0; ni < 4; ni++)
                    mma_tf32(sacc[mi][ni], qf[mi][kk], bf[ni]);
        }

        // ---- softmax phase 1: per-warp partial row max ----
        #pragma unroll
        for (int mi = 0; mi < 2; mi++) {
            #pragma unroll
            for (int half = 0; half < 2; half++) {
                float px = -1e30f;
                #pragma unroll
                for (int ni = 0; ni < 4; ni++) {
                    px = fmaxf(px, fmaxf(sacc[mi][ni][2 * half],
                                         sacc[mi][ni][2 * half + 1]));
                }
                px = fmaxf(px, __shfl_xor_sync(0xffffffff, px, 1));
                px = fmaxf(px, __shfl_xor_sync(0xffffffff, px, 2));
                if (tig == 0) {
                    const int row = wm * 32 + mi * 16 + half * 8 + gid;
                    Pmx[row * 2 + wn] = px;
                }
            }
        }
        __syncthreads();

        // ---- softmax phase 2: exp in registers, partial sums, O rescale ----
        #pragma unroll
        for (int mi = 0; mi < 2; mi++) {
            #pragma unroll
            for (int half = 0; half < 2; half++) {
                const int idx = mi * 2 + half;
                const int row = wm * 32 + mi * 16 + half * 8 + gid;
                const float mnew = fmaxf(mrun[idx],
                    fmaxf(Pmx[row * 2], Pmx[row * 2 + 1]));
                const float corr = fast_exp(mrun[idx] - mnew);
                mrun[idx] = mnew;
                lrun[idx] *= corr;
                float ps = 0.0f;
                #pragma unroll
                for (int ni = 0; ni < 4; ni++) {
                    float p0 = fast_exp(sacc[mi][ni][2 * half]     - mnew);
                    float p1 = fast_exp(sacc[mi][ni][2 * half + 1] - mnew);
                    sacc[mi][ni][2 * half]     = p0;
                    sacc[mi][ni][2 * half + 1] = p1;
                    ps += p0 + p1;
                    oacc[mi][ni][2 * half]     *= corr;
                    oacc[mi][ni][2 * half + 1] *= corr;
                }
                ps += __shfl_xor_sync(0xffffffff, ps, 1);
                ps += __shfl_xor_sync(0xffffffff, ps, 2);
                if (tig == 0) Psm[row * 2 + wn] = ps;
            }
        }

        // ---- write P (tf32) to smem for PV A-fragments ----
        #pragma unroll
        for (int mi = 0; mi < 2; mi++) {
            const int m = wm * 32 + mi * 16 + gid;
            #pragma unroll
            for (int ni = 0; ni < 4; ni++) {
                const int n = wn * 32 + ni * 8 + 2 * tig;
                *reinterpret_cast<float2*>(&S[m * SSTR + n]) = make_float2(
                    __int_as_float(f2tf32(sacc[mi][ni][0])),
                    __int_as_float(f2tf32(sacc[mi][ni][1])));
                *reinterpret_cast<float2*>(&S[(m + 8) * SSTR + n]) = make_float2(
                    __int_as_float(f2tf32(sacc[mi][ni][2])),
                    __int_as_float(f2tf32(sacc[mi][ni][3])));
            }
        }
        __syncthreads();

        // ---- finalize l with both warp partials ----
        #pragma unroll
        for (int mi = 0; mi < 2; mi++) {
            #pragma unroll
            for (int half = 0; half < 2; half++) {
                const int idx = mi * 2 + half;
                const int row = wm * 32 + mi * 16 + half * 8 + gid;
                lrun[idx] += Psm[row * 2] + Psm[row * 2 + 1];
            }
        }

        // ---- O += P @ V  (A-frags from S, B-frags from Vt) ----
        #pragma unroll
        for (int kk = 0; kk < 8; kk++) {
            const int kb = kk * 8;          // s-dim chunk
            uint32_t af[2][4], bf[4][2];
            #pragma unroll
            for (int mi = 0; mi < 2; mi++) {
                const int m = wm * 32 + mi * 16 + gid;
                af[mi][0] = __float_as_uint(S[(m    ) * SSTR + kb + tig    ]);
                af[mi][1] = __float_as_uint(S[(m + 8) * SSTR + kb + tig    ]);
                af[mi][2] = __float_as_uint(S[(m    ) * SSTR + kb + tig + 4]);
                af[mi][3] = __float_as_uint(S[(m + 8) * SSTR + kb + tig + 4]);
            }
            #pragma unroll
            for (int ni = 0; ni < 4; ni++) {
                const int n = wn * 32 + ni * 8 + gid;   // d-col
                bf[ni][0] = __float_as_uint(Vt[n * SSTR + kb + tig    ]);
                bf[ni][1] = __float_as_uint(Vt[n * SSTR + kb + tig + 4]);
            }
            #pragma unroll
            for (int mi = 0; mi < 2; mi++)
                #pragma unroll
                for (int ni = 0; ni < 4; ni++)
                    mma_tf32(oacc[mi][ni], af[mi], bf[ni]);
        }
    }

    // ---- epilogue: normalize by l, store ----
    #pragma unroll
    for (int mi = 0; mi < 2; mi++) {
        const int m = wm * 32 + mi * 16 + gid;
        const float il1 = 1.0f / lrun[mi * 2];
        const float il2 = 1.0f / lrun[mi * 2 + 1];
        #pragma unroll
        for (int ni = 0; ni < 4; ni++) {
            const int n = wn * 32 + ni * 8 + 2 * tig;
            float* y1 = &y[(size_t)(q0 + m) * C_DIM + h * D_DIM + n];
            float* y2 = &y[(size_t)(q0 + m + 8) * C_DIM + h * D_DIM + n];
            *reinterpret_cast<float2*>(y1) =
                make_float2(oacc[mi][ni][0] * il1, oacc[mi][ni][1] * il1);
            *reinterpret_cast<float2*>(y2) =
                make_float2(oacc[mi][ni][2] * il2, oacc[mi][ni][3] * il2);
        }
    }
}

// ---------------------------------------------------------------------------
// kernel_launch
// ---------------------------------------------------------------------------
extern "C" void kernel_launch(void* const* d_in, const int* in_sizes, int n_in,
                              void* d_out, int out_size)
{
    const float* x      = (const float*)d_in[0];
    const float* W_qkv  = (const float*)d_in[1];
    const float* b_qkv  = (const float*)d_in[2];
    const float* W_proj = (const float*)d_in[3];
    const float* b_proj = (const float*)d_in[4];
    float* out = (float*)d_out;

    float *qkv, *y;
    cudaGetSymbolAddress((void**)&qkv, g_qkv);
    cudaGetSymbolAddress((void**)&y, g_y);

    cudaFuncSetAttribute(gemm_tf32_bias,
        cudaFuncAttributeMaxDynamicSharedMemorySize, GEMM_SMEM);
    cudaFuncSetAttribute(attn_tc,
        cudaFuncAttributeMaxDynamicSharedMemorySize, ATTN_SMEM);

    gemm_tf32_bias<<<dim3(QKV_N / GBN, T_DIM / GBM), 256, GEMM_SMEM>>>(
        T_DIM, QKV_N, C_DIM, x, W_qkv, b_qkv, qkv);

    attn_tc<<<dim3(T_DIM / FA_M, H_DIM), 256, ATTN_SMEM>>>(qkv, y);

    gemm_tf32_bias<<<dim3(C_DIM / GBN, T_DIM / GBM), 256, GEMM_SMEM>>>(
        T_DIM, C_DIM, C_DIM, y, W_proj, b_proj, out);
}

// round 8
// speedup vs baseline: 3.6388x; 1.0765x over previous
#include <cuda_runtime.h>
#include <cuda_bf16.h>
#include <math.h>
#include <stdint.h>

// Problem constants
#define T_DIM 2048
#define C_DIM 1024
#define H_DIM 16
#define D_DIM 64
#define QKV_N (3 * C_DIM)   // 3072

// Scratch (allocation-free: __device__ globals)
__device__ float g_qkv[T_DIM * QKV_N];   // [T, 3C]
__device__ float g_y[T_DIM * C_DIM];     // [T, C] attention output

__device__ __forceinline__ uint32_t f2tf32(float x) {
    uint32_t r;
    asm("cvt.rna.tf32.f32 %0, %1;" : "=r"(r) : "f"(x));
    return r;
}

__device__ __forceinline__ void mma_tf32(float* d, const uint32_t* a, const uint32_t* b) {
    asm volatile(
        "mma.sync.aligned.m16n8k8.row.col.f32.tf32.tf32.f32 "
        "{%0,%1,%2,%3}, {%4,%5,%6,%7}, {%8,%9}, {%0,%1,%2,%3};"
        : "+f"(d[0]), "+f"(d[1]), "+f"(d[2]), "+f"(d[3])
        : "r"(a[0]), "r"(a[1]), "r"(a[2]), "r"(a[3]), "r"(b[0]), "r"(b[1]));
}

__device__ __forceinline__ uint32_t smem_u32(const void* p) {
    return (uint32_t)__cvta_generic_to_shared(p);
}
__device__ __forceinline__ void cp_async16(uint32_t dst, const void* src) {
    asm volatile("cp.async.cg.shared.global [%0], [%1], 16;" :: "r"(dst), "l"(src));
}
__device__ __forceinline__ void cp_commit() {
    asm volatile("cp.async.commit_group;");
}
template <int N>
__device__ __forceinline__ void cp_wait() {
    asm volatile("cp.async.wait_group %0;" :: "n"(N));
}

// ---------------------------------------------------------------------------
// TF32 tensor-core GEMM, double-buffered smem + register prefetch.
// C[M,N] = A[M,K] @ B[K,N] + bias[N]   (unchanged from R7)
// ---------------------------------------------------------------------------
#define GBM 128
#define GBN 128
#define GBK 32
#define AS_STRIDE 36
#define BS_STRIDE 136
#define AS_WORDS (GBM * AS_STRIDE)
#define BS_WORDS (GBK * BS_STRIDE)
#define GEMM_SMEM ((2 * AS_WORDS + 2 * BS_WORDS) * 4)

__global__ __launch_bounds__(256) void gemm_tf32_bias(
    int M, int N, int K,
    const float* __restrict__ A, const float* __restrict__ B,
    const float* __restrict__ bias, float* __restrict__ C)
{
    extern __shared__ uint32_t gsm[];
    uint32_t* AsBase = gsm;
    uint32_t* BsBase = gsm + 2 * AS_WORDS;

    const int tid  = threadIdx.x;
    const int lane = tid & 31;
    const int warp = tid >> 5;
    const int gid  = lane >> 2;
    const int tig  = lane & 3;

    const int wm = warp & 1;
    const int wn = warp >> 1;

    const int crow = blockIdx.y * GBM;
    const int ccol = blockIdx.x * GBN;

    const int arow  = tid >> 3;
    const int acol4 = tid & 7;
    const int brow32 = tid >> 5;
    const int bcol4  = tid & 31;

    float acc[4][4][4];
    #pragma unroll
    for (int i = 0; i < 4; i++)
        #pragma unroll
        for (int j = 0; j < 4; j++)
            #pragma unroll
            for (int r = 0; r < 4; r++) acc[i][j][r] = 0.0f;

    float4 aR[4], bR[4];

    #pragma unroll
    for (int p = 0; p < 4; p++) {
        aR[p] = *reinterpret_cast<const float4*>(
            &A[(size_t)(crow + arow + p * 32) * K + acol4 * 4]);
        bR[p] = *reinterpret_cast<const float4*>(
            &B[(size_t)(brow32 + p * 8) * N + ccol + bcol4 * 4]);
    }
    {
        uint32_t* As = AsBase;
        uint32_t* Bs = BsBase;
        #pragma unroll
        for (int p = 0; p < 4; p++) {
            uint32_t* da = &As[(arow + p * 32) * AS_STRIDE + acol4 * 4];
            da[0] = f2tf32(aR[p].x); da[1] = f2tf32(aR[p].y);
            da[2] = f2tf32(aR[p].z); da[3] = f2tf32(aR[p].w);
            uint32_t* db = &Bs[(brow32 + p * 8) * BS_STRIDE + bcol4 * 4];
            db[0] = f2tf32(bR[p].x); db[1] = f2tf32(bR[p].y);
            db[2] = f2tf32(bR[p].z); db[3] = f2tf32(bR[p].w);
        }
    }
    __syncthreads();

    int buf = 0;
    for (int k0 = 0; k0 < K; k0 += GBK) {
        const bool has_next = (k0 + GBK < K);
        if (has_next) {
            const int kn = k0 + GBK;
            #pragma unroll
            for (int p = 0; p < 4; p++) {
                aR[p] = *reinterpret_cast<const float4*>(
                    &A[(size_t)(crow + arow + p * 32) * K + kn + acol4 * 4]);
                bR[p] = *reinterpret_cast<const float4*>(
                    &B[(size_t)(kn + brow32 + p * 8) * N + ccol + bcol4 * 4]);
            }
        }

        uint32_t* As = AsBase + buf * AS_WORDS;
        uint32_t* Bs = BsBase + buf * BS_WORDS;
        #pragma unroll
        for (int kk = 0; kk < 4; kk++) {
            const int kb = kk * 8;
            uint32_t af[4][4], bf[4][2];
            #pragma unroll
            for (int mi = 0; mi < 4; mi++) {
                const int m = wm * 64 + mi * 16 + gid;
                af[mi][0] = As[(m    ) * AS_STRIDE + kb + tig    ];
                af[mi][1] = As[(m + 8) * AS_STRIDE + kb + tig    ];
                af[mi][2] = As[(m    ) * AS_STRIDE + kb + tig + 4];
                af[mi][3] = As[(m + 8) * AS_STRIDE + kb + tig + 4];
            }
            #pragma unroll
            for (int ni = 0; ni < 4; ni++) {
                const int n = wn * 32 + ni * 8 + gid;
                bf[ni][0] = Bs[(kb + tig    ) * BS_STRIDE + n];
                bf[ni][1] = Bs[(kb + tig + 4) * BS_STRIDE + n];
            }
            #pragma unroll
            for (int mi = 0; mi < 4; mi++)
                #pragma unroll
                for (int ni = 0; ni < 4; ni++)
                    mma_tf32(acc[mi][ni], af[mi], bf[ni]);
        }

        if (has_next) {
            uint32_t* Asn = AsBase + (buf ^ 1) * AS_WORDS;
            uint32_t* Bsn = BsBase + (buf ^ 1) * BS_WORDS;
            #pragma unroll
            for (int p = 0; p < 4; p++) {
                uint32_t* da = &Asn[(arow + p * 32) * AS_STRIDE + acol4 * 4];
                da[0] = f2tf32(aR[p].x); da[1] = f2tf32(aR[p].y);
                da[2] = f2tf32(aR[p].z); da[3] = f2tf32(aR[p].w);
                uint32_t* db = &Bsn[(brow32 + p * 8) * BS_STRIDE + bcol4 * 4];
                db[0] = f2tf32(bR[p].x); db[1] = f2tf32(bR[p].y);
                db[2] = f2tf32(bR[p].z); db[3] = f2tf32(bR[p].w);
            }
            __syncthreads();
            buf ^= 1;
        }
    }

    #pragma unroll
    for (int mi = 0; mi < 4; mi++) {
        const int r = crow + wm * 64 + mi * 16 + gid;
        #pragma unroll
        for (int ni = 0; ni < 4; ni++) {
            const int c = ccol + wn * 32 + ni * 8 + 2 * tig;
            const float b0 = bias[c], b1 = bias[c + 1];
            float2 o1 = make_float2(acc[mi][ni][0] + b0, acc[mi][ni][1] + b1);
            float2 o2 = make_float2(acc[mi][ni][2] + b0, acc[mi][ni][3] + b1);
            *reinterpret_cast<float2*>(&C[(size_t)r * N + c]) = o1;
            *reinterpret_cast<float2*>(&C[(size_t)(r + 8) * N + c]) = o2;
        }
    }
}

// ---------------------------------------------------------------------------
// Fast exp on FMA/ALU pipes only. Valid for x <= 0 (clamped). Rel err ~2e-6.
// ---------------------------------------------------------------------------
__device__ __forceinline__ float fast_exp(float x) {
    x = fmaxf(x, -87.3f);
    float z = x * 1.4426950408889634f;
    float t = z + 12582912.0f;
    int   n = __float_as_int(t);
    float fi = t - 12582912.0f;
    float f = z - fi;
    float p =          1.3534543e-3f;
    p = fmaf(p, f,     9.6178720e-3f);
    p = fmaf(p, f,     5.5503429e-2f);
    p = fmaf(p, f,     2.4022651e-1f);
    p = fmaf(p, f,     6.9314718e-1f);
    p = fmaf(p, f,     1.0f);
    int sb = (n << 23) + 0x3F800000;
    return p * __int_as_float(sb);
}

// ---------------------------------------------------------------------------
// Tensor-core flash attention, cp.async double-buffered K/V staging.
// - K and V staged RAW (no cvt, no transpose) via cp.async; tf32 RNA cvt
//   happens at fragment-load time (same math as before).
// - V used directly in [s][d] layout as the col-major B operand of PV.
// - K tile stride 68 (=4 mod 32), V tile stride 72 (=8 mod 32): both
//   fragment-read patterns are bank-conflict-free.
// ---------------------------------------------------------------------------
#define FA_M 128
#define FA_S 64
#define SSTR 68
#define KSTR 68
#define VSTR 72
#define KT_WORDS (FA_S * KSTR)   // 4352
#define VT_WORDS (FA_S * VSTR)   // 4608
// S[128*68] + 2*K + 2*V + Pmx[256] + Psm[256]
#define ATTN_SMEM ((128 * SSTR + 2 * KT_WORDS + 2 * VT_WORDS + 2 * 128 + 2 * 128) * 4)

__global__ __launch_bounds__(256) void attn_tc(
    const float* __restrict__ qkv, float* __restrict__ y)
{
    extern __shared__ float sm[];
    float* S     = sm;                         // [128][SSTR]  (Q staging, then P)
    float* Kbuf  = sm + 128 * SSTR;            // 2 x [64][KSTR] raw fp32
    float* Vbuf  = Kbuf + 2 * KT_WORDS;        // 2 x [64][VSTR] raw fp32
    float* Pmx   = Vbuf + 2 * VT_WORDS;        // [128][2]
    float* Psm   = Pmx + 2 * 128;              // [128][2]

    const int h  = blockIdx.y;
    const int q0 = blockIdx.x * FA_M;
    const int tid  = threadIdx.x;
    const int lane = tid & 31;
    const int warp = tid >> 5;
    const int gid  = lane >> 2;
    const int tig  = lane & 3;
    const int wm   = warp & 3;    // 0..3 -> 32 m-rows each
    const int wn   = warp >> 2;   // 0..1 -> 32 n-cols each

    const float* qbase = qkv + h * D_DIM;
    const float* kbase = qkv + C_DIM + h * D_DIM;
    const float* vbase = qkv + 2 * C_DIM + h * D_DIM;

    // ---- stage Q tile into S (tf32-rounded, pre-scaled by 1/8) ----
    for (int i = tid; i < FA_M * 16; i += 256) {
        const int r  = i >> 4;
        const int c4 = i & 15;
        float4 v = *reinterpret_cast<const float4*>(
            &qbase[(size_t)(q0 + r) * QKV_N + c4 * 4]);
        float* dst = &S[r * SSTR + c4 * 4];
        dst[0] = __int_as_float(f2tf32(v.x * 0.125f));
        dst[1] = __int_as_float(f2tf32(v.y * 0.125f));
        dst[2] = __int_as_float(f2tf32(v.z * 0.125f));
        dst[3] = __int_as_float(f2tf32(v.w * 0.125f));
    }

    // ---- prologue: async-stage K/V tile 0 into buffer 0 ----
    {
        #pragma unroll
        for (int p = 0; p < 4; p++) {
            const int idx = tid + p * 256;       // 0..1023
            const int r  = idx >> 4;
            const int c4 = idx & 15;
            cp_async16(smem_u32(&Kbuf[r * KSTR + c4 * 4]),
                       &kbase[(size_t)r * QKV_N + c4 * 4]);
            cp_async16(smem_u32(&Vbuf[r * VSTR + c4 * 4]),
                       &vbase[(size_t)r * QKV_N + c4 * 4]);
        }
        cp_commit();
    }
    __syncthreads();   // Q visible

    // ---- load persistent Q fragments ----
    uint32_t qf[2][8][4];
    #pragma unroll
    for (int mi = 0; mi < 2; mi++) {
        const int m = wm * 32 + mi * 16 + gid;
        #pragma unroll
        for (int kk = 0; kk < 8; kk++) {
            const int kb = kk * 8;
            qf[mi][kk][0] = __float_as_uint(S[(m    ) * SSTR + kb + tig    ]);
            qf[mi][kk][1] = __float_as_uint(S[(m + 8) * SSTR + kb + tig    ]);
            qf[mi][kk][2] = __float_as_uint(S[(m    ) * SSTR + kb + tig + 4]);
            qf[mi][kk][3] = __float_as_uint(S[(m + 8) * SSTR + kb + tig + 4]);
        }
    }

    float oacc[2][4][4];
    #pragma unroll
    for (int mi = 0; mi < 2; mi++)
        #pragma unroll
        for (int ni = 0; ni < 4; ni++)
            #pragma unroll
            for (int r = 0; r < 4; r++) oacc[mi][ni][r] = 0.0f;

    float mrun[4] = {-1e30f, -1e30f, -1e30f, -1e30f};
    float lrun[4] = {0.0f, 0.0f, 0.0f, 0.0f};

    int buf = 0;
    for (int it = 0; it < T_DIM / FA_S; it++) {
        // ---- async-stage next tile into the other buffer ----
        const bool has_next = (it + 1 < T_DIM / FA_S);
        if (has_next) {
            const int s0n = (it + 1) * FA_S;
            float* Kn = Kbuf + (buf ^ 1) * KT_WORDS;
            float* Vn = Vbuf + (buf ^ 1) * VT_WORDS;
            #pragma unroll
            for (int p = 0; p < 4; p++) {
                const int idx = tid + p * 256;
                const int r  = idx >> 4;
                const int c4 = idx & 15;
                cp_async16(smem_u32(&Kn[r * KSTR + c4 * 4]),
                           &kbase[(size_t)(s0n + r) * QKV_N + c4 * 4]);
                cp_async16(smem_u32(&Vn[r * VSTR + c4 * 4]),
                           &vbase[(size_t)(s0n + r) * QKV_N + c4 * 4]);
            }
            cp_commit();
            cp_wait<1>();   // current tile's group done; next still in flight
        } else {
            cp_wait<0>();
        }
        __syncthreads();    // current tile visible to all warps

        const float* Ks = Kbuf + buf * KT_WORDS;
        const float* Vs = Vbuf + buf * VT_WORDS;

        // ---- S = Q @ K^T  (M=128, N=64, K=64) ----
        float sacc[2][4][4];
        #pragma unroll
        for (int mi = 0; mi < 2; mi++)
            #pragma unroll
            for (int ni = 0; ni < 4; ni++)
                #pragma unroll
                for (int r = 0; r < 4; r++) sacc[mi][ni][r] = 0.0f;

        #pragma unroll
        for (int kk = 0; kk < 8; kk++) {
            const int kb = kk * 8;
            uint32_t bf[4][2];
            #pragma unroll
            for (int ni = 0; ni < 4; ni++) {
                const int n = wn * 32 + ni * 8 + gid;   // key row
                bf[ni][0] = f2tf32(Ks[n * KSTR + kb + tig    ]);
                bf[ni][1] = f2tf32(Ks[n * KSTR + kb + tig + 4]);
            }
            #pragma unroll
            for (int mi = 0; mi < 2; mi++)
                #pragma unroll
                for (int ni = 0; ni < 4; ni++)
                    mma_tf32(sacc[mi][ni], qf[mi][kk], bf[ni]);
        }

        // ---- softmax phase 1: per-warp partial row max ----
        #pragma unroll
        for (int mi = 0; mi < 2; mi++) {
            #pragma unroll
            for (int half = 0; half < 2; half++) {
                float px = -1e30f;
                #pragma unroll
                for (int ni = 0; ni < 4; ni++) {
                    px = fmaxf(px, fmaxf(sacc[mi][ni][2 * half],
                                         sacc[mi][ni][2 * half + 1]));
                }
                px = fmaxf(px, __shfl_xor_sync(0xffffffff, px, 1));
                px = fmaxf(px, __shfl_xor_sync(0xffffffff, px, 2));
                if (tig == 0) {
                    const int row = wm * 32 + mi * 16 + half * 8 + gid;
                    Pmx[row * 2 + wn] = px;
                }
            }
        }
        __syncthreads();

        // ---- softmax phase 2: exp in registers, partial sums, O rescale ----
        #pragma unroll
        for (int mi = 0; mi < 2; mi++) {
            #pragma unroll
            for (int half = 0; half < 2; half++) {
                const int idx = mi * 2 + half;
                const int row = wm * 32 + mi * 16 + half * 8 + gid;
                const float mnew = fmaxf(mrun[idx],
                    fmaxf(Pmx[row * 2], Pmx[row * 2 + 1]));
                const float corr = fast_exp(mrun[idx] - mnew);
                mrun[idx] = mnew;
                lrun[idx] *= corr;
                float ps = 0.0f;
                #pragma unroll
                for (int ni = 0; ni < 4; ni++) {
                    float p0 = fast_exp(sacc[mi][ni][2 * half]     - mnew);
                    float p1 = fast_exp(sacc[mi][ni][2 * half + 1] - mnew);
                    sacc[mi][ni][2 * half]     = p0;
                    sacc[mi][ni][2 * half + 1] = p1;
                    ps += p0 + p1;
                    oacc[mi][ni][2 * half]     *= corr;
                    oacc[mi][ni][2 * half + 1] *= corr;
                }
                ps += __shfl_xor_sync(0xffffffff, ps, 1);
                ps += __shfl_xor_sync(0xffffffff, ps, 2);
                if (tig == 0) Psm[row * 2 + wn] = ps;
            }
        }

        // ---- write P (tf32) to smem for PV A-fragments ----
        #pragma unroll
        for (int mi = 0; mi < 2; mi++) {
            const int m = wm * 32 + mi * 16 + gid;
            #pragma unroll
            for (int ni = 0; ni < 4; ni++) {
                const int n = wn * 32 + ni * 8 + 2 * tig;
                *reinterpret_cast<float2*>(&S[m * SSTR + n]) = make_float2(
                    __int_as_float(f2tf32(sacc[mi][ni][0])),
                    __int_as_float(f2tf32(sacc[mi][ni][1])));
                *reinterpret_cast<float2*>(&S[(m + 8) * SSTR + n]) = make_float2(
                    __int_as_float(f2tf32(sacc[mi][ni][2])),
                    __int_as_float(f2tf32(sacc[mi][ni][3])));
            }
        }
        __syncthreads();

        // ---- finalize l with both warp partials ----
        #pragma unroll
        for (int mi = 0; mi < 2; mi++) {
            #pragma unroll
            for (int half = 0; half < 2; half++) {
                const int idx = mi * 2 + half;
                const int row = wm * 32 + mi * 16 + half * 8 + gid;
                lrun[idx] += Psm[row * 2] + Psm[row * 2 + 1];
            }
        }

        // ---- O += P @ V  (A-frags from S, B-frags raw from Vs [s][d]) ----
        #pragma unroll
        for (int kk = 0; kk < 8; kk++) {
            const int kb = kk * 8;          // s-dim chunk
            uint32_t af[2][4], bf[4][2];
            #pragma unroll
            for (int mi = 0; mi < 2; mi++) {
                const int m = wm * 32 + mi * 16 + gid;
                af[mi][0] = __float_as_uint(S[(m    ) * SSTR + kb + tig    ]);
                af[mi][1] = __float_as_uint(S[(m + 8) * SSTR + kb + tig    ]);
                af[mi][2] = __float_as_uint(S[(m    ) * SSTR + kb + tig + 4]);
                af[mi][3] = __float_as_uint(S[(m + 8) * SSTR + kb + tig + 4]);
            }
            #pragma unroll
            for (int ni = 0; ni < 4; ni++) {
                const int n = wn * 32 + ni * 8 + gid;   // d-col
                bf[ni][0] = f2tf32(Vs[(kb + tig    ) * VSTR + n]);
                bf[ni][1] = f2tf32(Vs[(kb + tig + 4) * VSTR + n]);
            }
            #pragma unroll
            for (int mi = 0; mi < 2; mi++)
                #pragma unroll
                for (int ni = 0; ni < 4; ni++)
                    mma_tf32(oacc[mi][ni], af[mi], bf[ni]);
        }
        __syncthreads();   // all reads of current buffers done before overwrite
        buf ^= 1;
    }

    // ---- epilogue: normalize by l, store ----
    #pragma unroll
    for (int mi = 0; mi < 2; mi++) {
        const int m = wm * 32 + mi * 16 + gid;
        const float il1 = 1.0f / lrun[mi * 2];
        const float il2 = 1.0f / lrun[mi * 2 + 1];
        #pragma unroll
        for (int ni = 0; ni < 4; ni++) {
            const int n = wn * 32 + ni * 8 + 2 * tig;
            float* y1 = &y[(size_t)(q0 + m) * C_DIM + h * D_DIM + n];
            float* y2 = &y[(size_t)(q0 + m + 8) * C_DIM + h * D_DIM + n];
            *reinterpret_cast<float2*>(y1) =
                make_float2(oacc[mi][ni][0] * il1, oacc[mi][ni][1] * il1);
            *reinterpret_cast<float2*>(y2) =
                make_float2(oacc[mi][ni][2] * il2, oacc[mi][ni][3] * il2);
        }
    }
}

// ---------------------------------------------------------------------------
// kernel_launch
// ---------------------------------------------------------------------------
extern "C" void kernel_launch(void* const* d_in, const int* in_sizes, int n_in,
                              void* d_out, int out_size)
{
    const float* x      = (const float*)d_in[0];
    const float* W_qkv  = (const float*)d_in[1];
    const float* b_qkv  = (const float*)d_in[2];
    const float* W_proj = (const float*)d_in[3];
    const float* b_proj = (const float*)d_in[4];
    float* out = (float*)d_out;

    float *qkv, *y;
    cudaGetSymbolAddress((void**)&qkv, g_qkv);
    cudaGetSymbolAddress((void**)&y, g_y);

    cudaFuncSetAttribute(gemm_tf32_bias,
        cudaFuncAttributeMaxDynamicSharedMemorySize, GEMM_SMEM);
    cudaFuncSetAttribute(attn_tc,
        cudaFuncAttributeMaxDynamicSharedMemorySize, ATTN_SMEM);

    gemm_tf32_bias<<<dim3(QKV_N / GBN, T_DIM / GBM), 256, GEMM_SMEM>>>(
        T_DIM, QKV_N, C_DIM, x, W_qkv, b_qkv, qkv);

    attn_tc<<<dim3(T_DIM / FA_M, H_DIM), 256, ATTN_SMEM>>>(qkv, y);

    gemm_tf32_bias<<<dim3(C_DIM / GBN, T_DIM / GBM), 256, GEMM_SMEM>>>(
        T_DIM, C_DIM, C_DIM, y, W_proj, b_proj, out);
}